// round 2
// baseline (speedup 1.0000x reference)
#include <cuda_runtime.h>
#include <cstdint>

#define N_NODES 50000
#define N_EDGES 1600000
#define IN_DIM  1024
#define MID_DIM 256
#define MID_V4  (MID_DIM / 4)   // 64 float4 per row

// ---------------- scratch (device globals; no allocs allowed) ----------------
__device__ __align__(16) float g_deg[N_NODES];
__device__ __align__(16) float g_dis[N_NODES];
__device__ __align__(16) float g_xw  [(size_t)N_NODES * MID_DIM];  // x @ W1
__device__ __align__(16) float g_agg1[(size_t)N_NODES * MID_DIM];  // A_norm (x W1)
__device__ __align__(16) float g_agg2[(size_t)N_NODES * MID_DIM];  // A_norm relu(agg1+b1)
__device__ int g_is64;

// ---------------- edge-index dtype detection ----------------
// Reference declares int64, but JAX without x64 silently yields int32. Values are
// < 50000 and nonnegative, so for an int64 layout every odd 32-bit word is 0.
__global__ void detect_kernel(const int* __restrict__ ei_words) {
    if (threadIdx.x == 0 && blockIdx.x == 0) {
        int is64 = 1;
        #pragma unroll 1
        for (int i = 1; i < 512; i += 2)
            if (ei_words[i] != 0) { is64 = 0; break; }
        g_is64 = is64;
    }
}

__device__ __forceinline__ int edge_node(const void* ei, long long idx, int is64) {
    if (is64) return (int)((const long long*)ei)[idx];
    return ((const int*)ei)[idx];
}

// ---------------- degree / normalization ----------------
__global__ void deg_init_kernel() {
    int i = blockIdx.x * blockDim.x + threadIdx.x;
    if (i < N_NODES) g_deg[i] = 1.0f;  // self-loop
}

__global__ void deg_count_kernel(const void* __restrict__ ei) {
    int e = blockIdx.x * blockDim.x + threadIdx.x;
    if (e >= N_EDGES) return;
    int is64 = g_is64;
    int d = edge_node(ei, (long long)e + N_EDGES, is64);
    atomicAdd(&g_deg[d], 1.0f);
}

__global__ void dis_kernel() {
    int i = blockIdx.x * blockDim.x + threadIdx.x;
    if (i < N_NODES) g_dis[i] = rsqrtf(g_deg[i]);  // deg >= 1 always
}

// ---------------- SGEMM: C[M,N] = A[M,K] @ B[K,N] (+ bias) ----------------
// Classic 128x128x8 register-tiled fp32 GEMM, TM=TN=8, 256 threads.
template <bool USE_BIAS>
__global__ __launch_bounds__(256) void sgemm_kernel(
    const float* __restrict__ A, const float* __restrict__ B,
    const float* __restrict__ bias, float* __restrict__ C,
    int M, int N, int K)
{
    constexpr int BM = 128, BN = 128, BK = 8, TM = 8, TN = 8;
    __shared__ float As[BK][BM];
    __shared__ float Bs[BK][BN];

    const int tid  = threadIdx.x;
    const int cRow = blockIdx.y;
    const int cCol = blockIdx.x;
    const int tCol = tid % (BN / TN);  // 0..15
    const int tRow = tid / (BN / TN);  // 0..15

    // A tile: 128x8 = 256 float4, one per thread (transposed store)
    const int aRow = tid >> 1;          // 0..127
    const int aCol = (tid & 1) * 4;     // 0 or 4
    // B tile: 8x128 = 256 float4, one per thread
    const int bRow = tid >> 5;          // 0..7
    const int bCol = (tid & 31) * 4;    // 0..124

    float acc[TM][TN];
    #pragma unroll
    for (int i = 0; i < TM; i++)
        #pragma unroll
        for (int j = 0; j < TN; j++) acc[i][j] = 0.0f;

    const int rowBase = cRow * BM;
    float regM[TM], regN[TN];

    for (int k0 = 0; k0 < K; k0 += BK) {
        int gRow = rowBase + aRow;
        float4 av = (gRow < M)
            ? *(const float4*)(A + (size_t)gRow * K + k0 + aCol)
            : make_float4(0.f, 0.f, 0.f, 0.f);
        As[aCol + 0][aRow] = av.x;
        As[aCol + 1][aRow] = av.y;
        As[aCol + 2][aRow] = av.z;
        As[aCol + 3][aRow] = av.w;

        float4 bv = *(const float4*)(B + (size_t)(k0 + bRow) * N + cCol * BN + bCol);
        *(float4*)&Bs[bRow][bCol] = bv;
        __syncthreads();

        #pragma unroll
        for (int k = 0; k < BK; k++) {
            #pragma unroll
            for (int i = 0; i < TM; i++) regM[i] = As[k][tRow * TM + i];
            #pragma unroll
            for (int j = 0; j < TN; j++) regN[j] = Bs[k][tCol * TN + j];
            #pragma unroll
            for (int i = 0; i < TM; i++)
                #pragma unroll
                for (int j = 0; j < TN; j++)
                    acc[i][j] += regM[i] * regN[j];
        }
        __syncthreads();
    }

    #pragma unroll
    for (int i = 0; i < TM; i++) {
        int gRow = rowBase + tRow * TM + i;
        if (gRow >= M) continue;
        #pragma unroll
        for (int j = 0; j < TN; j += 4) {
            int gCol = cCol * BN + tCol * TN + j;
            float4 v = make_float4(acc[i][j], acc[i][j+1], acc[i][j+2], acc[i][j+3]);
            if (USE_BIAS) {
                v.x += bias[gCol + 0]; v.y += bias[gCol + 1];
                v.z += bias[gCol + 2]; v.w += bias[gCol + 3];
            }
            *(float4*)(C + (size_t)gRow * N + gCol) = v;
        }
    }
}

// ---------------- aggregation ----------------
// Self-loop initialization: dst[i,:] = f(src[i,:]) * dis[i]^2
template <bool RELU>
__global__ void agg_self_kernel(const float* __restrict__ src,
                                const float* __restrict__ b,
                                float* __restrict__ dst)
{
    int i = blockIdx.x * blockDim.x + threadIdx.x;  // over N_NODES * MID_V4
    if (i >= N_NODES * MID_V4) return;
    int node = i >> 6;
    float di = g_dis[node];
    float nn = di * di;
    float4 v = ((const float4*)src)[i];
    if (RELU) {
        float4 bb = ((const float4*)b)[i & (MID_V4 - 1)];
        v.x = fmaxf(v.x + bb.x, 0.f);
        v.y = fmaxf(v.y + bb.y, 0.f);
        v.z = fmaxf(v.z + bb.z, 0.f);
        v.w = fmaxf(v.w + bb.w, 0.f);
    }
    v.x *= nn; v.y *= nn; v.z *= nn; v.w *= nn;
    ((float4*)dst)[i] = v;
}

__device__ __forceinline__ void red_add_v4(float* addr, float4 v) {
    asm volatile("red.global.add.v4.f32 [%0], {%1, %2, %3, %4};"
                 :: "l"(addr), "f"(v.x), "f"(v.y), "f"(v.z), "f"(v.w)
                 : "memory");
}

// Edge scatter: warp per edge; dst[d,:] += f(src[s,:]) * dis[s]*dis[d]
template <bool RELU>
__global__ __launch_bounds__(256) void agg_edges_kernel(
    const void* __restrict__ ei,
    const float* __restrict__ srcfeat,
    const float* __restrict__ b,
    float* __restrict__ dstfeat)
{
    int warp = blockIdx.x * (blockDim.x >> 5) + (threadIdx.x >> 5);
    int lane = threadIdx.x & 31;
    if (warp >= N_EDGES) return;

    int s = 0, d = 0;
    float nrm = 0.f;
    if (lane == 0) {
        int is64 = g_is64;
        s = edge_node(ei, warp, is64);
        d = edge_node(ei, (long long)warp + N_EDGES, is64);
        nrm = g_dis[s] * g_dis[d];
    }
    s   = __shfl_sync(0xffffffffu, s, 0);
    d   = __shfl_sync(0xffffffffu, d, 0);
    nrm = __shfl_sync(0xffffffffu, nrm, 0);

    const float4* srow = (const float4*)(srcfeat + (size_t)s * MID_DIM);
    float*        drow = dstfeat + (size_t)d * MID_DIM;

    #pragma unroll
    for (int j = 0; j < 2; j++) {
        int c = lane + j * 32;  // 0..63
        float4 v = __ldg(srow + c);
        if (RELU) {
            float4 bb = *(const float4*)(b + 4 * c);
            v.x = fmaxf(v.x + bb.x, 0.f);
            v.y = fmaxf(v.y + bb.y, 0.f);
            v.z = fmaxf(v.z + bb.z, 0.f);
            v.w = fmaxf(v.w + bb.w, 0.f);
        }
        v.x *= nrm; v.y *= nrm; v.z *= nrm; v.w *= nrm;
        red_add_v4(drow + 4 * c, v);
    }
}

// ---------------- launch ----------------
extern "C" void kernel_launch(void* const* d_in, const int* in_sizes, int n_in,
                              void* d_out, int out_size)
{
    const float* x  = (const float*)d_in[0];
    const void*  ei = d_in[1];                 // [2, N_EDGES] int64 or int32
    const float* W1 = (const float*)d_in[2];
    const float* b1 = (const float*)d_in[3];
    const float* W2 = (const float*)d_in[4];
    const float* b2 = (const float*)d_in[5];
    float* out = (float*)d_out;

    float *xw, *agg1, *agg2;
    cudaGetSymbolAddress((void**)&xw,   g_xw);
    cudaGetSymbolAddress((void**)&agg1, g_agg1);
    cudaGetSymbolAddress((void**)&agg2, g_agg2);

    // 1. edge dtype detection
    detect_kernel<<<1, 32>>>((const int*)ei);

    // 2. degree / dis
    deg_init_kernel<<<(N_NODES + 255) / 256, 256>>>();
    deg_count_kernel<<<(N_EDGES + 255) / 256, 256>>>(ei);
    dis_kernel<<<(N_NODES + 255) / 256, 256>>>();

    // 3. xw = x @ W1   [50000,1024]x[1024,256]
    {
        dim3 grid(MID_DIM / 128, (N_NODES + 127) / 128);
        sgemm_kernel<false><<<grid, 256>>>(x, W1, nullptr, xw,
                                           N_NODES, MID_DIM, IN_DIM);
    }

    // 4. agg1 = A_norm xw (self init + edge scatter)
    agg_self_kernel<false><<<(N_NODES * MID_V4 + 255) / 256, 256>>>(xw, nullptr, agg1);
    agg_edges_kernel<false><<<(N_EDGES * 32 + 255) / 256, 256>>>(ei, xw, nullptr, agg1);

    // 5. agg2 = A_norm relu(agg1 + b1)  (relu+bias fused into the gather)
    agg_self_kernel<true><<<(N_NODES * MID_V4 + 255) / 256, 256>>>(agg1, b1, agg2);
    agg_edges_kernel<true><<<(N_EDGES * 32 + 255) / 256, 256>>>(ei, agg1, b1, agg2);

    // 6. out = agg2 @ W2 + b2   [50000,256]x[256,1024]
    {
        dim3 grid(IN_DIM / 128, (N_NODES + 127) / 128);
        sgemm_kernel<true><<<grid, 256>>>(agg2, W2, b2, out,
                                          N_NODES, IN_DIM, MID_DIM);
    }
}

// round 5
// speedup vs baseline: 1.8077x; 1.8077x over previous
#include <cuda_runtime.h>
#include <cstdint>

#define N_NODES 50000
#define N_EDGES 1600000
#define IN_DIM  1024
#define MID_DIM 256
#define MID_V4  (MID_DIM / 4)

// ---------------- scratch (device globals; no allocs allowed) ----------------
__device__ __align__(16) float g_deg[N_NODES];
__device__ __align__(16) float g_dis[N_NODES];
__device__ __align__(16) float g_xw  [(size_t)N_NODES * MID_DIM];
__device__ __align__(16) float g_agg1[(size_t)N_NODES * MID_DIM];
__device__ __align__(16) float g_agg2[(size_t)N_NODES * MID_DIM];
__device__ int g_is64;

// ---------------- helpers ----------------
__device__ __forceinline__ uint32_t cvt_tf32(float x) {
    uint32_t r; asm("cvt.rna.tf32.f32 %0, %1;" : "=r"(r) : "f"(x)); return r;
}

__device__ __forceinline__ void mma_tf32(float& c0, float& c1, float& c2, float& c3,
                                         uint32_t a0, uint32_t a1, uint32_t a2, uint32_t a3,
                                         uint32_t b0, uint32_t b1) {
    asm volatile(
        "mma.sync.aligned.m16n8k8.row.col.f32.tf32.tf32.f32 "
        "{%0,%1,%2,%3}, {%4,%5,%6,%7}, {%8,%9}, {%0,%1,%2,%3};"
        : "+f"(c0), "+f"(c1), "+f"(c2), "+f"(c3)
        : "r"(a0), "r"(a1), "r"(a2), "r"(a3), "r"(b0), "r"(b1));
}

// ---------------- edge-index dtype detection ----------------
__global__ void detect_kernel(const int* __restrict__ ei_words) {
    if (threadIdx.x == 0 && blockIdx.x == 0) {
        int is64 = 1;
        #pragma unroll 1
        for (int i = 1; i < 512; i += 2)
            if (ei_words[i] != 0) { is64 = 0; break; }
        g_is64 = is64;
    }
}
__device__ __forceinline__ int edge_node(const void* ei, long long idx, int is64) {
    if (is64) return (int)((const long long*)ei)[idx];
    return ((const int*)ei)[idx];
}

// ---------------- degree / normalization ----------------
__global__ void deg_init_kernel() {
    int i = blockIdx.x * blockDim.x + threadIdx.x;
    if (i < N_NODES) g_deg[i] = 1.0f;
}
__global__ void deg_count_kernel(const void* __restrict__ ei) {
    int e = blockIdx.x * blockDim.x + threadIdx.x;
    if (e >= N_EDGES) return;
    int d = edge_node(ei, (long long)e + N_EDGES, g_is64);
    atomicAdd(&g_deg[d], 1.0f);
}
__global__ void dis_kernel() {
    int i = blockIdx.x * blockDim.x + threadIdx.x;
    if (i < N_NODES) g_dis[i] = rsqrtf(g_deg[i]);
}

// ---------------- tf32 mma.sync GEMM ----------------
// C[M,N] = A[M,K] @ B[K,N] (+bias). BM=128, BN=128, BK=16.
// 8 warps: warp_m = wid&1 (64 rows), warp_n = wid>>1 (32 cols).
// Each warp: 4x4 grid of m16n8k8 mma, 2 k-steps per tile.
// As[m][k] stride 20 / Bs[k][n] stride 136: conflict-free fragment LDS.
// WRITE_SELF: additionally writes Cself = C * dis[row]^2 (layer-1 self-loop fused).
template <bool USE_BIAS, bool WRITE_SELF>
__global__ __launch_bounds__(256) void gemm_mma_kernel(
    const float* __restrict__ A, const float* __restrict__ B,
    const float* __restrict__ bias, float* __restrict__ C,
    float* __restrict__ Cself, int M, int N, int K)
{
    __shared__ uint32_t As[2][128][20];   // [buf][m][k], pad->stride 20
    __shared__ uint32_t Bs[2][16][136];   // [buf][k][n], pad->stride 136

    const int tid  = threadIdx.x;
    const int wid  = tid >> 5;
    const int lane = tid & 31;
    const int warp_m = wid & 1;
    const int warp_n = wid >> 1;
    const int rowBase = blockIdx.y * 128;
    const int colBase = blockIdx.x * 128;
    const int KT = K / 16;

    // staging indices
    const int am = tid >> 2;            // A: rows tid/4, tid/4+64... wait: idx up to 511
    const int akq = tid & 3;
    const int br = tid >> 5;            // B: row tid/32 (+8 for second chunk)
    const int bc = (tid & 31) * 4;

    float4 ra[2], rb[2];
    const float4 fz = make_float4(0.f, 0.f, 0.f, 0.f);

    auto load_regs = [&](int t) {
        const int k0 = t * 16;
        #pragma unroll
        for (int i = 0; i < 2; i++) {
            int m = am + i * 64;
            int gr = rowBase + m;
            ra[i] = (gr < M) ? __ldg((const float4*)(A + (size_t)gr * K + k0 + akq * 4)) : fz;
            rb[i] = __ldg((const float4*)(B + (size_t)(k0 + br + i * 8) * N + colBase + bc));
        }
    };
    auto sts = [&](int buf) {
        #pragma unroll
        for (int i = 0; i < 2; i++) {
            uint4 va = make_uint4(cvt_tf32(ra[i].x), cvt_tf32(ra[i].y),
                                  cvt_tf32(ra[i].z), cvt_tf32(ra[i].w));
            *(uint4*)&As[buf][am + i * 64][akq * 4] = va;
            uint4 vb = make_uint4(cvt_tf32(rb[i].x), cvt_tf32(rb[i].y),
                                  cvt_tf32(rb[i].z), cvt_tf32(rb[i].w));
            *(uint4*)&Bs[buf][br + i * 8][bc] = vb;
        }
    };

    float acc[4][4][4];
    #pragma unroll
    for (int i = 0; i < 4; i++)
        #pragma unroll
        for (int j = 0; j < 4; j++)
            #pragma unroll
            for (int r = 0; r < 4; r++) acc[i][j][r] = 0.f;

    const int lg = lane >> 2;   // 0..7
    const int lr = lane & 3;    // 0..3

    load_regs(0);
    sts(0);
    __syncthreads();

    for (int t = 0; t < KT; t++) {
        const int buf = t & 1;
        if (t + 1 < KT) load_regs(t + 1);

        #pragma unroll
        for (int ks = 0; ks < 2; ks++) {
            const int k0s = ks * 8;
            uint32_t af[4][4], bf[4][2];
            #pragma unroll
            for (int i = 0; i < 4; i++) {
                int m0 = warp_m * 64 + i * 16;
                af[i][0] = As[buf][m0 + lg][k0s + lr];
                af[i][1] = As[buf][m0 + lg + 8][k0s + lr];
                af[i][2] = As[buf][m0 + lg][k0s + lr + 4];
                af[i][3] = As[buf][m0 + lg + 8][k0s + lr + 4];
            }
            #pragma unroll
            for (int j = 0; j < 4; j++) {
                int n0 = warp_n * 32 + j * 8;
                bf[j][0] = Bs[buf][k0s + lr][n0 + lg];
                bf[j][1] = Bs[buf][k0s + lr + 4][n0 + lg];
            }
            #pragma unroll
            for (int i = 0; i < 4; i++)
                #pragma unroll
                for (int j = 0; j < 4; j++)
                    mma_tf32(acc[i][j][0], acc[i][j][1], acc[i][j][2], acc[i][j][3],
                             af[i][0], af[i][1], af[i][2], af[i][3],
                             bf[j][0], bf[j][1]);
        }

        if (t + 1 < KT) {
            sts(buf ^ 1);
            __syncthreads();
        }
    }

    // epilogue
    #pragma unroll
    for (int i = 0; i < 4; i++) {
        const int r0 = rowBase + warp_m * 64 + i * 16 + lg;
        #pragma unroll
        for (int half = 0; half < 2; half++) {
            const int rr = r0 + half * 8;
            if (rr >= M) continue;
            float nn = 0.f;
            if (WRITE_SELF) { float di = g_dis[rr]; nn = di * di; }
            #pragma unroll
            for (int j = 0; j < 4; j++) {
                const int cc = colBase + warp_n * 32 + j * 8 + lr * 2;
                float v0 = acc[i][j][half * 2 + 0];
                float v1 = acc[i][j][half * 2 + 1];
                if (USE_BIAS) { v0 += bias[cc]; v1 += bias[cc + 1]; }
                *(float2*)(C + (size_t)rr * N + cc) = make_float2(v0, v1);
                if (WRITE_SELF)
                    *(float2*)(Cself + (size_t)rr * N + cc) = make_float2(v0 * nn, v1 * nn);
            }
        }
    }
}

// ---------------- aggregation ----------------
// Self-loop init for layer 2: dst[i,:] = relu(src[i,:] + b) * dis[i]^2
__global__ void agg_self_relu_kernel(const float* __restrict__ src,
                                     const float* __restrict__ b,
                                     float* __restrict__ dst)
{
    int i = blockIdx.x * blockDim.x + threadIdx.x;
    if (i >= N_NODES * MID_V4) return;
    int node = i >> 6;
    float di = g_dis[node];
    float nn = di * di;
    float4 v = ((const float4*)src)[i];
    float4 bb = ((const float4*)b)[i & (MID_V4 - 1)];
    v.x = fmaxf(v.x + bb.x, 0.f) * nn;
    v.y = fmaxf(v.y + bb.y, 0.f) * nn;
    v.z = fmaxf(v.z + bb.z, 0.f) * nn;
    v.w = fmaxf(v.w + bb.w, 0.f) * nn;
    ((float4*)dst)[i] = v;
}

__device__ __forceinline__ void red_add_v4(float* addr, float4 v) {
    asm volatile("red.global.add.v4.f32 [%0], {%1, %2, %3, %4};"
                 :: "l"(addr), "f"(v.x), "f"(v.y), "f"(v.z), "f"(v.w)
                 : "memory");
}

template <bool RELU>
__global__ __launch_bounds__(256) void agg_edges_kernel(
    const void* __restrict__ ei,
    const float* __restrict__ srcfeat,
    const float* __restrict__ b,
    float* __restrict__ dstfeat)
{
    int warp = blockIdx.x * (blockDim.x >> 5) + (threadIdx.x >> 5);
    int lane = threadIdx.x & 31;
    if (warp >= N_EDGES) return;

    int s = 0, d = 0;
    float nrm = 0.f;
    if (lane == 0) {
        int is64 = g_is64;
        s = edge_node(ei, warp, is64);
        d = edge_node(ei, (long long)warp + N_EDGES, is64);
        nrm = g_dis[s] * g_dis[d];
    }
    s   = __shfl_sync(0xffffffffu, s, 0);
    d   = __shfl_sync(0xffffffffu, d, 0);
    nrm = __shfl_sync(0xffffffffu, nrm, 0);

    const float4* srow = (const float4*)(srcfeat + (size_t)s * MID_DIM);
    float*        drow = dstfeat + (size_t)d * MID_DIM;

    #pragma unroll
    for (int j = 0; j < 2; j++) {
        int c = lane + j * 32;
        float4 v = __ldg(srow + c);
        if (RELU) {
            float4 bb = *(const float4*)(b + 4 * c);
            v.x = fmaxf(v.x + bb.x, 0.f);
            v.y = fmaxf(v.y + bb.y, 0.f);
            v.z = fmaxf(v.z + bb.z, 0.f);
            v.w = fmaxf(v.w + bb.w, 0.f);
        }
        v.x *= nrm; v.y *= nrm; v.z *= nrm; v.w *= nrm;
        red_add_v4(drow + 4 * c, v);
    }
}

// ---------------- launch ----------------
extern "C" void kernel_launch(void* const* d_in, const int* in_sizes, int n_in,
                              void* d_out, int out_size)
{
    const float* x  = (const float*)d_in[0];
    const void*  ei = d_in[1];
    const float* W1 = (const float*)d_in[2];
    const float* b1 = (const float*)d_in[3];
    const float* W2 = (const float*)d_in[4];
    const float* b2 = (const float*)d_in[5];
    float* out = (float*)d_out;

    float *xw, *agg1, *agg2;
    cudaGetSymbolAddress((void**)&xw,   g_xw);
    cudaGetSymbolAddress((void**)&agg1, g_agg1);
    cudaGetSymbolAddress((void**)&agg2, g_agg2);

    // 1. edge dtype detection + degree/dis
    detect_kernel<<<1, 32>>>((const int*)ei);
    deg_init_kernel<<<(N_NODES + 255) / 256, 256>>>();
    deg_count_kernel<<<(N_EDGES + 255) / 256, 256>>>(ei);
    dis_kernel<<<(N_NODES + 255) / 256, 256>>>();

    const int mblocks = (N_NODES + 127) / 128;  // 391

    // 2. xw = x @ W1 ; agg1 = xw * dis^2 (self-loop fused into epilogue)
    gemm_mma_kernel<false, true><<<dim3(MID_DIM / 128, mblocks), 256>>>(
        x, W1, nullptr, xw, agg1, N_NODES, MID_DIM, IN_DIM);

    // 3. agg1 += edges (gather xw)
    agg_edges_kernel<false><<<(N_EDGES * 32 + 255) / 256, 256>>>(ei, xw, nullptr, agg1);

    // 4. agg2 = relu(agg1 + b1) * dis^2 ; then edges with fused relu+bias gather
    agg_self_relu_kernel<<<(N_NODES * MID_V4 + 255) / 256, 256>>>(agg1, b1, agg2);
    agg_edges_kernel<true><<<(N_EDGES * 32 + 255) / 256, 256>>>(ei, agg1, b1, agg2);

    // 5. out = agg2 @ W2 + b2
    gemm_mma_kernel<true, false><<<dim3(IN_DIM / 128, mblocks), 256>>>(
        agg2, W2, b2, out, nullptr, N_NODES, IN_DIM, MID_DIM);
}

// round 6
// speedup vs baseline: 2.8434x; 1.5729x over previous
#include <cuda_runtime.h>
#include <cstdint>

#define N_NODES 50000
#define N_EDGES 1600000
#define IN_DIM  1024
#define MID_DIM 256
#define MID_V4  (MID_DIM / 4)
#define NBLK_SCAN ((N_NODES + 255) / 256)   // 196

// ---------------- scratch (device globals; no allocs allowed) ----------------
__device__ __align__(16) float  g_dis[N_NODES];
__device__ __align__(16) float  g_xw  [(size_t)N_NODES * MID_DIM];
__device__ __align__(16) float  g_agg1[(size_t)N_NODES * MID_DIM];
__device__ __align__(16) float  g_agg2[(size_t)N_NODES * MID_DIM];
__device__ int    g_cnt[N_NODES];       // in-degree (excluding self loop)
__device__ int    g_rowptr[N_NODES];    // CSR row start (exclusive scan of cnt)
__device__ int    g_cur[N_NODES];       // scatter cursors
__device__ int    g_bsum[NBLK_SCAN];
__device__ __align__(8) float2 g_epack[N_EDGES];  // {src_as_float_bits, norm}
__device__ int    g_is64;

// ---------------- helpers ----------------
__device__ __forceinline__ uint32_t cvt_tf32(float x) {
    uint32_t r; asm("cvt.rna.tf32.f32 %0, %1;" : "=r"(r) : "f"(x)); return r;
}
__device__ __forceinline__ void mma_tf32(float& c0, float& c1, float& c2, float& c3,
                                         uint32_t a0, uint32_t a1, uint32_t a2, uint32_t a3,
                                         uint32_t b0, uint32_t b1) {
    asm volatile(
        "mma.sync.aligned.m16n8k8.row.col.f32.tf32.tf32.f32 "
        "{%0,%1,%2,%3}, {%4,%5,%6,%7}, {%8,%9}, {%0,%1,%2,%3};"
        : "+f"(c0), "+f"(c1), "+f"(c2), "+f"(c3)
        : "r"(a0), "r"(a1), "r"(a2), "r"(a3), "r"(b0), "r"(b1));
}

// ---------------- edge-index dtype detection ----------------
__global__ void detect_kernel(const int* __restrict__ ei_words) {
    if (threadIdx.x == 0 && blockIdx.x == 0) {
        int is64 = 1;
        #pragma unroll 1
        for (int i = 1; i < 512; i += 2)
            if (ei_words[i] != 0) { is64 = 0; break; }
        g_is64 = is64;
    }
}
__device__ __forceinline__ int edge_node(const void* ei, long long idx, int is64) {
    if (is64) return (int)((const long long*)ei)[idx];
    return ((const int*)ei)[idx];
}

// ---------------- CSR build ----------------
__global__ void zero_cnt_kernel() {
    int i = blockIdx.x * blockDim.x + threadIdx.x;
    if (i < N_NODES) g_cnt[i] = 0;
}
__global__ void hist_kernel(const void* __restrict__ ei) {
    int e = blockIdx.x * blockDim.x + threadIdx.x;
    if (e >= N_EDGES) return;
    int d = edge_node(ei, (long long)e + N_EDGES, g_is64);
    atomicAdd(&g_cnt[d], 1);
}
__global__ void dis_kernel() {
    int i = blockIdx.x * blockDim.x + threadIdx.x;
    if (i < N_NODES) g_dis[i] = rsqrtf((float)(g_cnt[i] + 1));  // +1 self loop
}
// blockwise inclusive scan of g_cnt -> g_rowptr, block totals -> g_bsum
__global__ void scan1_kernel() {
    __shared__ int sh[256];
    int i = blockIdx.x * 256 + threadIdx.x;
    int v = (i < N_NODES) ? g_cnt[i] : 0;
    sh[threadIdx.x] = v;
    __syncthreads();
    #pragma unroll
    for (int off = 1; off < 256; off <<= 1) {
        int t = (threadIdx.x >= off) ? sh[threadIdx.x - off] : 0;
        __syncthreads();
        sh[threadIdx.x] += t;
        __syncthreads();
    }
    if (i < N_NODES) g_rowptr[i] = sh[threadIdx.x];
    if (threadIdx.x == 255) g_bsum[blockIdx.x] = sh[255];
}
// exclusive scan of block sums (single block)
__global__ void scan2_kernel() {
    __shared__ int sh[256];
    int v = (threadIdx.x < NBLK_SCAN) ? g_bsum[threadIdx.x] : 0;
    sh[threadIdx.x] = v;
    __syncthreads();
    #pragma unroll
    for (int off = 1; off < 256; off <<= 1) {
        int t = (threadIdx.x >= off) ? sh[threadIdx.x - off] : 0;
        __syncthreads();
        sh[threadIdx.x] += t;
        __syncthreads();
    }
    if (threadIdx.x < NBLK_SCAN) g_bsum[threadIdx.x] = sh[threadIdx.x] - v;
}
// inclusive -> exclusive + block offset; init cursors
__global__ void scan3_kernel() {
    int i = blockIdx.x * 256 + threadIdx.x;
    if (i < N_NODES) {
        int ex = g_rowptr[i] - g_cnt[i] + g_bsum[blockIdx.x];
        g_rowptr[i] = ex;
        g_cur[i] = ex;
    }
}
__global__ void scatter_kernel(const void* __restrict__ ei) {
    int e = blockIdx.x * blockDim.x + threadIdx.x;
    if (e >= N_EDGES) return;
    int is64 = g_is64;
    int s = edge_node(ei, e, is64);
    int d = edge_node(ei, (long long)e + N_EDGES, is64);
    int pos = atomicAdd(&g_cur[d], 1);
    g_epack[pos] = make_float2(__int_as_float(s), g_dis[s] * g_dis[d]);
}

// ---------------- tf32 mma.sync GEMM ----------------
template <bool USE_BIAS>
__global__ __launch_bounds__(256) void gemm_mma_kernel(
    const float* __restrict__ A, const float* __restrict__ B,
    const float* __restrict__ bias, float* __restrict__ C,
    int M, int N, int K)
{
    __shared__ uint32_t As[2][128][20];
    __shared__ uint32_t Bs[2][16][136];

    const int tid  = threadIdx.x;
    const int wid  = tid >> 5;
    const int lane = tid & 31;
    const int warp_m = wid & 1;
    const int warp_n = wid >> 1;
    const int rowBase = blockIdx.y * 128;
    const int colBase = blockIdx.x * 128;
    const int KT = K / 16;

    const int am = tid >> 2;
    const int akq = tid & 3;
    const int br = tid >> 5;
    const int bc = (tid & 31) * 4;

    float4 ra[2], rb[2];
    const float4 fz = make_float4(0.f, 0.f, 0.f, 0.f);

    auto load_regs = [&](int t) {
        const int k0 = t * 16;
        #pragma unroll
        for (int i = 0; i < 2; i++) {
            int gr = rowBase + am + i * 64;
            ra[i] = (gr < M) ? __ldg((const float4*)(A + (size_t)gr * K + k0 + akq * 4)) : fz;
            rb[i] = __ldg((const float4*)(B + (size_t)(k0 + br + i * 8) * N + colBase + bc));
        }
    };
    auto sts = [&](int buf) {
        #pragma unroll
        for (int i = 0; i < 2; i++) {
            uint4 va = make_uint4(cvt_tf32(ra[i].x), cvt_tf32(ra[i].y),
                                  cvt_tf32(ra[i].z), cvt_tf32(ra[i].w));
            *(uint4*)&As[buf][am + i * 64][akq * 4] = va;
            uint4 vb = make_uint4(cvt_tf32(rb[i].x), cvt_tf32(rb[i].y),
                                  cvt_tf32(rb[i].z), cvt_tf32(rb[i].w));
            *(uint4*)&Bs[buf][br + i * 8][bc] = vb;
        }
    };

    float acc[4][4][4];
    #pragma unroll
    for (int i = 0; i < 4; i++)
        #pragma unroll
        for (int j = 0; j < 4; j++)
            #pragma unroll
            for (int r = 0; r < 4; r++) acc[i][j][r] = 0.f;

    const int lg = lane >> 2;
    const int lr = lane & 3;

    load_regs(0);
    sts(0);
    __syncthreads();

    for (int t = 0; t < KT; t++) {
        const int buf = t & 1;
        if (t + 1 < KT) load_regs(t + 1);

        #pragma unroll
        for (int ks = 0; ks < 2; ks++) {
            const int k0s = ks * 8;
            uint32_t af[4][4], bf[4][2];
            #pragma unroll
            for (int i = 0; i < 4; i++) {
                int m0 = warp_m * 64 + i * 16;
                af[i][0] = As[buf][m0 + lg][k0s + lr];
                af[i][1] = As[buf][m0 + lg + 8][k0s + lr];
                af[i][2] = As[buf][m0 + lg][k0s + lr + 4];
                af[i][3] = As[buf][m0 + lg + 8][k0s + lr + 4];
            }
            #pragma unroll
            for (int j = 0; j < 4; j++) {
                int n0 = warp_n * 32 + j * 8;
                bf[j][0] = Bs[buf][k0s + lr][n0 + lg];
                bf[j][1] = Bs[buf][k0s + lr + 4][n0 + lg];
            }
            #pragma unroll
            for (int i = 0; i < 4; i++)
                #pragma unroll
                for (int j = 0; j < 4; j++)
                    mma_tf32(acc[i][j][0], acc[i][j][1], acc[i][j][2], acc[i][j][3],
                             af[i][0], af[i][1], af[i][2], af[i][3],
                             bf[j][0], bf[j][1]);
        }

        if (t + 1 < KT) {
            sts(buf ^ 1);
            __syncthreads();
        }
    }

    #pragma unroll
    for (int i = 0; i < 4; i++) {
        const int r0 = rowBase + warp_m * 64 + i * 16 + lg;
        #pragma unroll
        for (int half = 0; half < 2; half++) {
            const int rr = r0 + half * 8;
            if (rr >= M) continue;
            #pragma unroll
            for (int j = 0; j < 4; j++) {
                const int cc = colBase + warp_n * 32 + j * 8 + lr * 2;
                float v0 = acc[i][j][half * 2 + 0];
                float v1 = acc[i][j][half * 2 + 1];
                if (USE_BIAS) { v0 += bias[cc]; v1 += bias[cc + 1]; }
                *(float2*)(C + (size_t)rr * N + cc) = make_float2(v0, v1);
            }
        }
    }
}

// ---------------- CSR gather aggregation ----------------
// warp per destination node:
//   dst[d,:] = f(src[d,:])*dis[d]^2 + sum_e  norm_e * f(src[srcidx_e,:])
// f = identity (layer 1) or relu(.+b1) (layer 2). Single plain store, no atomics.
template <bool RELU>
__global__ __launch_bounds__(256) void gather_kernel(
    const float* __restrict__ srcfeat,
    const float* __restrict__ bias,
    float* __restrict__ dstfeat)
{
    const int warp = blockIdx.x * 8 + (threadIdx.x >> 5);
    const int lane = threadIdx.x & 31;
    if (warp >= N_NODES) return;

    const int start = g_rowptr[warp];
    const int end   = start + g_cnt[warp];
    const float di  = g_dis[warp];
    const float nn  = di * di;

    float4 bb0, bb1;
    if (RELU) {
        bb0 = ((const float4*)bias)[lane];
        bb1 = ((const float4*)bias)[lane + 32];
    }

    // self term
    float4 a0, a1;
    {
        const float4* srow = (const float4*)(srcfeat + (size_t)warp * MID_DIM);
        float4 v0 = __ldg(srow + lane);
        float4 v1 = __ldg(srow + lane + 32);
        if (RELU) {
            v0.x = fmaxf(v0.x + bb0.x, 0.f); v0.y = fmaxf(v0.y + bb0.y, 0.f);
            v0.z = fmaxf(v0.z + bb0.z, 0.f); v0.w = fmaxf(v0.w + bb0.w, 0.f);
            v1.x = fmaxf(v1.x + bb1.x, 0.f); v1.y = fmaxf(v1.y + bb1.y, 0.f);
            v1.z = fmaxf(v1.z + bb1.z, 0.f); v1.w = fmaxf(v1.w + bb1.w, 0.f);
        }
        a0 = make_float4(v0.x * nn, v0.y * nn, v0.z * nn, v0.w * nn);
        a1 = make_float4(v1.x * nn, v1.y * nn, v1.z * nn, v1.w * nn);
    }

    // edges: chunked cooperative fetch + shfl broadcast
    for (int base = start; base < end; base += 32) {
        const int rem = min(32, end - base);
        float2 ep = make_float2(0.f, 0.f);
        if (base + lane < end) ep = __ldg(&g_epack[base + lane]);
        #pragma unroll 4
        for (int j = 0; j < rem; j++) {
            const int   s = __shfl_sync(0xffffffffu, __float_as_int(ep.x), j);
            const float w = __shfl_sync(0xffffffffu, ep.y, j);
            const float4* r = (const float4*)(srcfeat + (size_t)s * MID_DIM);
            float4 u0 = __ldg(r + lane);
            float4 u1 = __ldg(r + lane + 32);
            if (RELU) {
                u0.x = fmaxf(u0.x + bb0.x, 0.f); u0.y = fmaxf(u0.y + bb0.y, 0.f);
                u0.z = fmaxf(u0.z + bb0.z, 0.f); u0.w = fmaxf(u0.w + bb0.w, 0.f);
                u1.x = fmaxf(u1.x + bb1.x, 0.f); u1.y = fmaxf(u1.y + bb1.y, 0.f);
                u1.z = fmaxf(u1.z + bb1.z, 0.f); u1.w = fmaxf(u1.w + bb1.w, 0.f);
            }
            a0.x = fmaf(w, u0.x, a0.x); a0.y = fmaf(w, u0.y, a0.y);
            a0.z = fmaf(w, u0.z, a0.z); a0.w = fmaf(w, u0.w, a0.w);
            a1.x = fmaf(w, u1.x, a1.x); a1.y = fmaf(w, u1.y, a1.y);
            a1.z = fmaf(w, u1.z, a1.z); a1.w = fmaf(w, u1.w, a1.w);
        }
    }

    float4* drow = (float4*)(dstfeat + (size_t)warp * MID_DIM);
    drow[lane]      = a0;
    drow[lane + 32] = a1;
}

// ---------------- launch ----------------
extern "C" void kernel_launch(void* const* d_in, const int* in_sizes, int n_in,
                              void* d_out, int out_size)
{
    const float* x  = (const float*)d_in[0];
    const void*  ei = d_in[1];
    const float* W1 = (const float*)d_in[2];
    const float* b1 = (const float*)d_in[3];
    const float* W2 = (const float*)d_in[4];
    const float* b2 = (const float*)d_in[5];
    float* out = (float*)d_out;

    float *xw, *agg1, *agg2;
    cudaGetSymbolAddress((void**)&xw,   g_xw);
    cudaGetSymbolAddress((void**)&agg1, g_agg1);
    cudaGetSymbolAddress((void**)&agg2, g_agg2);

    const int nb_nodes = (N_NODES + 255) / 256;
    const int nb_edges = (N_EDGES + 255) / 256;

    // CSR build
    detect_kernel<<<1, 32>>>((const int*)ei);
    zero_cnt_kernel<<<nb_nodes, 256>>>();
    hist_kernel<<<nb_edges, 256>>>(ei);
    dis_kernel<<<nb_nodes, 256>>>();
    scan1_kernel<<<NBLK_SCAN, 256>>>();
    scan2_kernel<<<1, 256>>>();
    scan3_kernel<<<NBLK_SCAN, 256>>>();
    scatter_kernel<<<nb_edges, 256>>>(ei);

    const int mblocks = (N_NODES + 127) / 128;
    const int gblocks = (N_NODES + 7) / 8;   // warp per node, 8 warps/block

    // layer 1
    gemm_mma_kernel<false><<<dim3(MID_DIM / 128, mblocks), 256>>>(
        x, W1, nullptr, xw, N_NODES, MID_DIM, IN_DIM);
    gather_kernel<false><<<gblocks, 256>>>(xw, nullptr, agg1);

    // layer 2
    gather_kernel<true><<<gblocks, 256>>>(agg1, b1, agg2);
    gemm_mma_kernel<true><<<dim3(IN_DIM / 128, mblocks), 256>>>(
        agg2, W2, b2, out, N_NODES, IN_DIM, MID_DIM);
}

// round 7
// speedup vs baseline: 3.1806x; 1.1186x over previous
#include <cuda_runtime.h>
#include <cuda_fp16.h>
#include <cstdint>

#define N_NODES 50000
#define N_EDGES 1600000
#define IN_DIM  1024
#define MID_DIM 256
#define NBLK_SCAN ((N_NODES + 255) / 256)   // 196

// ---------------- scratch (device globals; no allocs allowed) ----------------
__device__ __align__(16) float  g_dis[N_NODES];
__device__ __align__(16) __half g_xw  [(size_t)N_NODES * MID_DIM];  // x@W1, fp16
__device__ __align__(16) __half g_h   [(size_t)N_NODES * MID_DIM];  // relu(A xw + b1), fp16
__device__ __align__(16) float  g_agg2[(size_t)N_NODES * MID_DIM];  // A h, fp32
__device__ int    g_cnt[N_NODES];
__device__ int    g_rowptr[N_NODES];
__device__ int    g_cur[N_NODES];
__device__ int    g_bsum[NBLK_SCAN];
__device__ __align__(8) float2 g_epack[N_EDGES];  // {src_as_float_bits, norm}
__device__ int    g_is64;

// ---------------- helpers ----------------
__device__ __forceinline__ uint32_t cvt_tf32(float x) {
    uint32_t r; asm("cvt.rna.tf32.f32 %0, %1;" : "=r"(r) : "f"(x)); return r;
}
__device__ __forceinline__ void mma_tf32(float& c0, float& c1, float& c2, float& c3,
                                         uint32_t a0, uint32_t a1, uint32_t a2, uint32_t a3,
                                         uint32_t b0, uint32_t b1) {
    asm volatile(
        "mma.sync.aligned.m16n8k8.row.col.f32.tf32.tf32.f32 "
        "{%0,%1,%2,%3}, {%4,%5,%6,%7}, {%8,%9}, {%0,%1,%2,%3};"
        : "+f"(c0), "+f"(c1), "+f"(c2), "+f"(c3)
        : "r"(a0), "r"(a1), "r"(a2), "r"(a3), "r"(b0), "r"(b1));
}

// ---------------- edge-index dtype detection ----------------
__global__ void detect_kernel(const int* __restrict__ ei_words) {
    if (threadIdx.x == 0 && blockIdx.x == 0) {
        int is64 = 1;
        #pragma unroll 1
        for (int i = 1; i < 512; i += 2)
            if (ei_words[i] != 0) { is64 = 0; break; }
        g_is64 = is64;
    }
}
__device__ __forceinline__ int edge_node(const void* ei, long long idx, int is64) {
    if (is64) return (int)((const long long*)ei)[idx];
    return ((const int*)ei)[idx];
}

// ---------------- CSR build ----------------
__global__ void zero_cnt_kernel() {
    int i = blockIdx.x * blockDim.x + threadIdx.x;
    if (i < N_NODES) g_cnt[i] = 0;
}
__global__ void hist_kernel(const void* __restrict__ ei) {
    int e = blockIdx.x * blockDim.x + threadIdx.x;
    if (e >= N_EDGES) return;
    int d = edge_node(ei, (long long)e + N_EDGES, g_is64);
    atomicAdd(&g_cnt[d], 1);
}
__global__ void dis_kernel() {
    int i = blockIdx.x * blockDim.x + threadIdx.x;
    if (i < N_NODES) g_dis[i] = rsqrtf((float)(g_cnt[i] + 1));
}
__global__ void scan1_kernel() {
    __shared__ int sh[256];
    int i = blockIdx.x * 256 + threadIdx.x;
    int v = (i < N_NODES) ? g_cnt[i] : 0;
    sh[threadIdx.x] = v;
    __syncthreads();
    #pragma unroll
    for (int off = 1; off < 256; off <<= 1) {
        int t = (threadIdx.x >= off) ? sh[threadIdx.x - off] : 0;
        __syncthreads();
        sh[threadIdx.x] += t;
        __syncthreads();
    }
    if (i < N_NODES) g_rowptr[i] = sh[threadIdx.x];
    if (threadIdx.x == 255) g_bsum[blockIdx.x] = sh[255];
}
__global__ void scan2_kernel() {
    __shared__ int sh[256];
    int v = (threadIdx.x < NBLK_SCAN) ? g_bsum[threadIdx.x] : 0;
    sh[threadIdx.x] = v;
    __syncthreads();
    #pragma unroll
    for (int off = 1; off < 256; off <<= 1) {
        int t = (threadIdx.x >= off) ? sh[threadIdx.x - off] : 0;
        __syncthreads();
        sh[threadIdx.x] += t;
        __syncthreads();
    }
    if (threadIdx.x < NBLK_SCAN) g_bsum[threadIdx.x] = sh[threadIdx.x] - v;
}
__global__ void scan3_kernel() {
    int i = blockIdx.x * 256 + threadIdx.x;
    if (i < N_NODES) {
        int ex = g_rowptr[i] - g_cnt[i] + g_bsum[blockIdx.x];
        g_rowptr[i] = ex;
        g_cur[i] = ex;
    }
}
__global__ void scatter_kernel(const void* __restrict__ ei) {
    int e = blockIdx.x * blockDim.x + threadIdx.x;
    if (e >= N_EDGES) return;
    int is64 = g_is64;
    int s = edge_node(ei, e, is64);
    int d = edge_node(ei, (long long)e + N_EDGES, is64);
    int pos = atomicAdd(&g_cur[d], 1);
    g_epack[pos] = make_float2(__int_as_float(s), g_dis[s] * g_dis[d]);
}

// ---------------- tf32 mma.sync GEMM ----------------
// OUT_HALF: C is __half* (xw path). Otherwise float* (+optional bias).
template <bool USE_BIAS, bool OUT_HALF>
__global__ __launch_bounds__(256) void gemm_mma_kernel(
    const float* __restrict__ A, const float* __restrict__ B,
    const float* __restrict__ bias, void* __restrict__ Cv,
    int M, int N, int K)
{
    __shared__ uint32_t As[2][128][20];
    __shared__ uint32_t Bs[2][16][136];

    const int tid  = threadIdx.x;
    const int wid  = tid >> 5;
    const int lane = tid & 31;
    const int warp_m = wid & 1;
    const int warp_n = wid >> 1;
    const int rowBase = blockIdx.y * 128;
    const int colBase = blockIdx.x * 128;
    const int KT = K / 16;

    const int am = tid >> 2;
    const int akq = tid & 3;
    const int br = tid >> 5;
    const int bc = (tid & 31) * 4;

    float4 ra[2], rb[2];
    const float4 fz = make_float4(0.f, 0.f, 0.f, 0.f);

    auto load_regs = [&](int t) {
        const int k0 = t * 16;
        #pragma unroll
        for (int i = 0; i < 2; i++) {
            int gr = rowBase + am + i * 64;
            ra[i] = (gr < M) ? __ldg((const float4*)(A + (size_t)gr * K + k0 + akq * 4)) : fz;
            rb[i] = __ldg((const float4*)(B + (size_t)(k0 + br + i * 8) * N + colBase + bc));
        }
    };
    auto sts = [&](int buf) {
        #pragma unroll
        for (int i = 0; i < 2; i++) {
            uint4 va = make_uint4(cvt_tf32(ra[i].x), cvt_tf32(ra[i].y),
                                  cvt_tf32(ra[i].z), cvt_tf32(ra[i].w));
            *(uint4*)&As[buf][am + i * 64][akq * 4] = va;
            uint4 vb = make_uint4(cvt_tf32(rb[i].x), cvt_tf32(rb[i].y),
                                  cvt_tf32(rb[i].z), cvt_tf32(rb[i].w));
            *(uint4*)&Bs[buf][br + i * 8][bc] = vb;
        }
    };

    float acc[4][4][4];
    #pragma unroll
    for (int i = 0; i < 4; i++)
        #pragma unroll
        for (int j = 0; j < 4; j++)
            #pragma unroll
            for (int r = 0; r < 4; r++) acc[i][j][r] = 0.f;

    const int lg = lane >> 2;
    const int lr = lane & 3;

    load_regs(0);
    sts(0);
    __syncthreads();

    for (int t = 0; t < KT; t++) {
        const int buf = t & 1;
        if (t + 1 < KT) load_regs(t + 1);

        #pragma unroll
        for (int ks = 0; ks < 2; ks++) {
            const int k0s = ks * 8;
            uint32_t af[4][4], bf[4][2];
            #pragma unroll
            for (int i = 0; i < 4; i++) {
                int m0 = warp_m * 64 + i * 16;
                af[i][0] = As[buf][m0 + lg][k0s + lr];
                af[i][1] = As[buf][m0 + lg + 8][k0s + lr];
                af[i][2] = As[buf][m0 + lg][k0s + lr + 4];
                af[i][3] = As[buf][m0 + lg + 8][k0s + lr + 4];
            }
            #pragma unroll
            for (int j = 0; j < 4; j++) {
                int n0 = warp_n * 32 + j * 8;
                bf[j][0] = Bs[buf][k0s + lr][n0 + lg];
                bf[j][1] = Bs[buf][k0s + lr + 4][n0 + lg];
            }
            #pragma unroll
            for (int i = 0; i < 4; i++)
                #pragma unroll
                for (int j = 0; j < 4; j++)
                    mma_tf32(acc[i][j][0], acc[i][j][1], acc[i][j][2], acc[i][j][3],
                             af[i][0], af[i][1], af[i][2], af[i][3],
                             bf[j][0], bf[j][1]);
        }

        if (t + 1 < KT) {
            sts(buf ^ 1);
            __syncthreads();
        }
    }

    #pragma unroll
    for (int i = 0; i < 4; i++) {
        const int r0 = rowBase + warp_m * 64 + i * 16 + lg;
        #pragma unroll
        for (int half = 0; half < 2; half++) {
            const int rr = r0 + half * 8;
            if (rr >= M) continue;
            #pragma unroll
            for (int j = 0; j < 4; j++) {
                const int cc = colBase + warp_n * 32 + j * 8 + lr * 2;
                float v0 = acc[i][j][half * 2 + 0];
                float v1 = acc[i][j][half * 2 + 1];
                if (USE_BIAS) { v0 += bias[cc]; v1 += bias[cc + 1]; }
                if (OUT_HALF) {
                    __half2* C = (__half2*)Cv;
                    C[((size_t)rr * N + cc) >> 1] = __floats2half2_rn(v0, v1);
                } else {
                    float* C = (float*)Cv;
                    *(float2*)(C + (size_t)rr * N + cc) = make_float2(v0, v1);
                }
            }
        }
    }
}

// ---------------- CSR gather aggregation (fp16 in, fp32 accumulate) ----------------
// warp per destination; lane owns 8 consecutive features (one uint4 = 8 halves).
// L1: out = relu(agg + b1) -> fp16.   L2: out = agg -> fp32.
template <bool L1>
__global__ __launch_bounds__(256) void gather_kernel(
    const __half* __restrict__ srcfeat,
    const float* __restrict__ bias,
    __half* __restrict__ out_h,
    float* __restrict__ out_f)
{
    const int warp = blockIdx.x * 8 + (threadIdx.x >> 5);
    const int lane = threadIdx.x & 31;
    if (warp >= N_NODES) return;

    const int start = g_rowptr[warp];
    const int end   = start + g_cnt[warp];
    const float di  = g_dis[warp];
    const float nn  = di * di;

    float acc[8];

    // self term
    {
        uint4 raw = __ldg((const uint4*)(srcfeat + (size_t)warp * MID_DIM) + lane);
        const __half2* hp = (const __half2*)&raw;
        #pragma unroll
        for (int q = 0; q < 4; q++) {
            float2 f = __half22float2(hp[q]);
            acc[2 * q]     = f.x * nn;
            acc[2 * q + 1] = f.y * nn;
        }
    }

    // edges: chunked cooperative fetch + shfl broadcast
    for (int base = start; base < end; base += 32) {
        const int rem = min(32, end - base);
        float2 ep = make_float2(0.f, 0.f);
        if (base + lane < end) ep = __ldg(&g_epack[base + lane]);
        #pragma unroll 4
        for (int j = 0; j < rem; j++) {
            const int   s = __shfl_sync(0xffffffffu, __float_as_int(ep.x), j);
            const float w = __shfl_sync(0xffffffffu, ep.y, j);
            uint4 raw = __ldg((const uint4*)(srcfeat + (size_t)s * MID_DIM) + lane);
            const __half2* hp = (const __half2*)&raw;
            #pragma unroll
            for (int q = 0; q < 4; q++) {
                float2 f = __half22float2(hp[q]);
                acc[2 * q]     = fmaf(w, f.x, acc[2 * q]);
                acc[2 * q + 1] = fmaf(w, f.y, acc[2 * q + 1]);
            }
        }
    }

    const int c8 = lane * 8;
    if (L1) {
        // h = relu(acc + b1), fp16 out
        float4 bb0 = *(const float4*)(bias + c8);
        float4 bb1 = *(const float4*)(bias + c8 + 4);
        const float* bp = &bb0.x;
        uint4 outv;
        __half2* op = (__half2*)&outv;
        #pragma unroll
        for (int q = 0; q < 4; q++) {
            float v0 = fmaxf(acc[2 * q]     + ((const float*)&bb0)[0], 0.f);
            float v1 = fmaxf(acc[2 * q + 1] + 0.f, 0.f);
            // (indices resolved below; placeholder removed)
            op[q] = __floats2half2_rn(v0, v1);
        }
        // NOTE: rewritten without placeholder:
        float b[8] = {bb0.x, bb0.y, bb0.z, bb0.w, bb1.x, bb1.y, bb1.z, bb1.w};
        #pragma unroll
        for (int q = 0; q < 4; q++) {
            float v0 = fmaxf(acc[2 * q]     + b[2 * q],     0.f);
            float v1 = fmaxf(acc[2 * q + 1] + b[2 * q + 1], 0.f);
            op[q] = __floats2half2_rn(v0, v1);
        }
        (void)bp;
        ((uint4*)(out_h + (size_t)warp * MID_DIM))[lane] = outv;
    } else {
        float4 o0 = make_float4(acc[0], acc[1], acc[2], acc[3]);
        float4 o1 = make_float4(acc[4], acc[5], acc[6], acc[7]);
        float4* drow = (float4*)(out_f + (size_t)warp * MID_DIM);
        drow[2 * lane]     = o0;
        drow[2 * lane + 1] = o1;
    }
}

// ---------------- launch ----------------
extern "C" void kernel_launch(void* const* d_in, const int* in_sizes, int n_in,
                              void* d_out, int out_size)
{
    const float* x  = (const float*)d_in[0];
    const void*  ei = d_in[1];
    const float* W1 = (const float*)d_in[2];
    const float* b1 = (const float*)d_in[3];
    const float* W2 = (const float*)d_in[4];
    const float* b2 = (const float*)d_in[5];
    float* out = (float*)d_out;

    __half *xw, *h;
    float *agg2;
    cudaGetSymbolAddress((void**)&xw,   g_xw);
    cudaGetSymbolAddress((void**)&h,    g_h);
    cudaGetSymbolAddress((void**)&agg2, g_agg2);

    const int nb_nodes = (N_NODES + 255) / 256;
    const int nb_edges = (N_EDGES + 255) / 256;

    // CSR build
    detect_kernel<<<1, 32>>>((const int*)ei);
    zero_cnt_kernel<<<nb_nodes, 256>>>();
    hist_kernel<<<nb_edges, 256>>>(ei);
    dis_kernel<<<nb_nodes, 256>>>();
    scan1_kernel<<<NBLK_SCAN, 256>>>();
    scan2_kernel<<<1, 256>>>();
    scan3_kernel<<<NBLK_SCAN, 256>>>();
    scatter_kernel<<<nb_edges, 256>>>(ei);

    const int mblocks = (N_NODES + 127) / 128;
    const int gblocks = (N_NODES + 7) / 8;

    // layer 1: xw = x@W1 (fp16 out); h = relu(A_norm xw + b1) (fp16 out)
    gemm_mma_kernel<false, true><<<dim3(MID_DIM / 128, mblocks), 256>>>(
        x, W1, nullptr, xw, N_NODES, MID_DIM, IN_DIM);
    gather_kernel<true><<<gblocks, 256>>>(xw, b1, h, nullptr);

    // layer 2: agg2 = A_norm h (fp32); out = agg2@W2 + b2
    gather_kernel<false><<<gblocks, 256>>>(h, nullptr, nullptr, agg2);
    gemm_mma_kernel<true, false><<<dim3(IN_DIM / 128, mblocks), 256>>>(
        agg2, W2, b2, out, N_NODES, IN_DIM, MID_DIM);
}

// round 8
// speedup vs baseline: 4.1529x; 1.3057x over previous
#include <cuda_runtime.h>
#include <cuda_fp16.h>
#include <cstdint>

#define N_NODES 50000
#define N_EDGES 1600000
#define IN_DIM  1024
#define MID_DIM 256
#define NBLK_SCAN ((N_NODES + 255) / 256)   // 196

// ---------------- scratch (device globals; no allocs allowed) ----------------
__device__ __align__(16) float  g_dis[N_NODES];
__device__ __align__(16) __half g_xw  [(size_t)N_NODES * MID_DIM];  // x@W1, fp16
__device__ __align__(16) __half g_h   [(size_t)N_NODES * MID_DIM];  // relu(A xw + b1), fp16
__device__ __align__(16) float  g_agg2[(size_t)N_NODES * MID_DIM];  // A h, fp32
__device__ int    g_cnt[N_NODES];
__device__ int    g_rowptr[N_NODES];
__device__ int    g_cur[N_NODES];
__device__ int    g_bsum[NBLK_SCAN];
__device__ __align__(8) float2 g_epack[N_EDGES];  // {src_as_float_bits, norm}
__device__ int    g_is64;

// ---------------- helpers ----------------
__device__ __forceinline__ uint32_t smem_u32(const void* p) {
    uint32_t a;
    asm("{ .reg .u64 t; cvta.to.shared.u64 t, %1; cvt.u32.u64 %0, t; }"
        : "=r"(a) : "l"(p));
    return a;
}
__device__ __forceinline__ void ldmatrix_x4(uint32_t* r, uint32_t addr) {
    asm volatile("ldmatrix.sync.aligned.m8n8.x4.shared.b16 {%0,%1,%2,%3}, [%4];"
                 : "=r"(r[0]), "=r"(r[1]), "=r"(r[2]), "=r"(r[3]) : "r"(addr));
}
__device__ __forceinline__ void ldmatrix_x2t(uint32_t* r, uint32_t addr) {
    asm volatile("ldmatrix.sync.aligned.m8n8.x2.trans.shared.b16 {%0,%1}, [%2];"
                 : "=r"(r[0]), "=r"(r[1]) : "r"(addr));
}
__device__ __forceinline__ void mma_f16(float* c, const uint32_t* a, const uint32_t* b) {
    asm volatile(
        "mma.sync.aligned.m16n8k16.row.col.f32.f16.f16.f32 "
        "{%0,%1,%2,%3}, {%4,%5,%6,%7}, {%8,%9}, {%0,%1,%2,%3};"
        : "+f"(c[0]), "+f"(c[1]), "+f"(c[2]), "+f"(c[3])
        : "r"(a[0]), "r"(a[1]), "r"(a[2]), "r"(a[3]), "r"(b[0]), "r"(b[1]));
}

// ---------------- edge-index dtype detection ----------------
__global__ void detect_kernel(const int* __restrict__ ei_words) {
    if (threadIdx.x == 0 && blockIdx.x == 0) {
        int is64 = 1;
        #pragma unroll 1
        for (int i = 1; i < 512; i += 2)
            if (ei_words[i] != 0) { is64 = 0; break; }
        g_is64 = is64;
    }
}
__device__ __forceinline__ int edge_node(const void* ei, long long idx, int is64) {
    if (is64) return (int)((const long long*)ei)[idx];
    return ((const int*)ei)[idx];
}

// ---------------- CSR build ----------------
__global__ void zero_cnt_kernel() {
    int i = blockIdx.x * blockDim.x + threadIdx.x;
    if (i < N_NODES) g_cnt[i] = 0;
}
__global__ void hist_kernel(const void* __restrict__ ei) {
    int e = blockIdx.x * blockDim.x + threadIdx.x;
    if (e >= N_EDGES) return;
    int d = edge_node(ei, (long long)e + N_EDGES, g_is64);
    atomicAdd(&g_cnt[d], 1);
}
__global__ void dis_kernel() {
    int i = blockIdx.x * blockDim.x + threadIdx.x;
    if (i < N_NODES) g_dis[i] = rsqrtf((float)(g_cnt[i] + 1));
}
__global__ void scan1_kernel() {
    __shared__ int sh[256];
    int i = blockIdx.x * 256 + threadIdx.x;
    int v = (i < N_NODES) ? g_cnt[i] : 0;
    sh[threadIdx.x] = v;
    __syncthreads();
    #pragma unroll
    for (int off = 1; off < 256; off <<= 1) {
        int t = (threadIdx.x >= off) ? sh[threadIdx.x - off] : 0;
        __syncthreads();
        sh[threadIdx.x] += t;
        __syncthreads();
    }
    if (i < N_NODES) g_rowptr[i] = sh[threadIdx.x];
    if (threadIdx.x == 255) g_bsum[blockIdx.x] = sh[255];
}
__global__ void scan2_kernel() {
    __shared__ int sh[256];
    int v = (threadIdx.x < NBLK_SCAN) ? g_bsum[threadIdx.x] : 0;
    sh[threadIdx.x] = v;
    __syncthreads();
    #pragma unroll
    for (int off = 1; off < 256; off <<= 1) {
        int t = (threadIdx.x >= off) ? sh[threadIdx.x - off] : 0;
        __syncthreads();
        sh[threadIdx.x] += t;
        __syncthreads();
    }
    if (threadIdx.x < NBLK_SCAN) g_bsum[threadIdx.x] = sh[threadIdx.x] - v;
}
__global__ void scan3_kernel() {
    int i = blockIdx.x * 256 + threadIdx.x;
    if (i < N_NODES) {
        int ex = g_rowptr[i] - g_cnt[i] + g_bsum[blockIdx.x];
        g_rowptr[i] = ex;
        g_cur[i] = ex;
    }
}
__global__ void scatter_kernel(const void* __restrict__ ei) {
    int e = blockIdx.x * blockDim.x + threadIdx.x;
    if (e >= N_EDGES) return;
    int is64 = g_is64;
    int s = edge_node(ei, e, is64);
    int d = edge_node(ei, (long long)e + N_EDGES, is64);
    int pos = atomicAdd(&g_cur[d], 1);
    g_epack[pos] = make_float2(__int_as_float(s), g_dis[s] * g_dis[d]);
}

// ---------------- fp16 mma.sync GEMM ----------------
// C[M,N] = A[M,K] @ B[K,N] (+bias). BM=128, BN=128, BK=16, fp32 accumulate.
// 8 warps: warp_m = wid&1 (64 rows), warp_n = wid>>1 (32 cols).
// Each warp: 4x4 grid of m16n8k16. ldmatrix from padded smem (A stride 24h=48B,
// B stride 136h=272B) -> conflict-free fragment loads.
template <bool USE_BIAS, bool OUT_HALF>
__global__ __launch_bounds__(256) void gemm_f16_kernel(
    const float* __restrict__ A, const float* __restrict__ B,
    const float* __restrict__ bias, void* __restrict__ Cv,
    int M, int N, int K)
{
    __shared__ __half As[2][128][24];
    __shared__ __half Bs[2][16][136];

    const int tid  = threadIdx.x;
    const int wid  = tid >> 5;
    const int lane = tid & 31;
    const int warp_m = wid & 1;
    const int warp_n = wid >> 1;
    const int rowBase = blockIdx.y * 128;
    const int colBase = blockIdx.x * 128;
    const int KT = K / 16;

    const int am = tid >> 2;            // 0..63 (A rows am, am+64)
    const int akq = tid & 3;            // k quad (4 floats)
    const int br = tid >> 5;            // 0..7  (B rows br, br+8)
    const int bc = (tid & 31) * 4;      // 0..124

    float4 ra[2], rb[2];
    const float4 fz = make_float4(0.f, 0.f, 0.f, 0.f);

    auto load_regs = [&](int t) {
        const int k0 = t * 16;
        #pragma unroll
        for (int i = 0; i < 2; i++) {
            int gr = rowBase + am + i * 64;
            ra[i] = (gr < M) ? __ldg((const float4*)(A + (size_t)gr * K + k0 + akq * 4)) : fz;
            rb[i] = __ldg((const float4*)(B + (size_t)(k0 + br + i * 8) * N + colBase + bc));
        }
    };
    auto sts = [&](int buf) {
        #pragma unroll
        for (int i = 0; i < 2; i++) {
            uint2 va;
            ((__half2*)&va)[0] = __floats2half2_rn(ra[i].x, ra[i].y);
            ((__half2*)&va)[1] = __floats2half2_rn(ra[i].z, ra[i].w);
            *(uint2*)&As[buf][am + i * 64][akq * 4] = va;
            uint2 vb;
            ((__half2*)&vb)[0] = __floats2half2_rn(rb[i].x, rb[i].y);
            ((__half2*)&vb)[1] = __floats2half2_rn(rb[i].z, rb[i].w);
            *(uint2*)&Bs[buf][br + i * 8][bc] = vb;
        }
    };

    float acc[4][4][4];
    #pragma unroll
    for (int i = 0; i < 4; i++)
        #pragma unroll
        for (int j = 0; j < 4; j++)
            #pragma unroll
            for (int r = 0; r < 4; r++) acc[i][j][r] = 0.f;

    // ldmatrix per-lane source addresses
    const uint32_t a_base = smem_u32(&As[0][0][0]);
    const uint32_t b_base = smem_u32(&Bs[0][0][0]);
    const uint32_t a_stride = 128 * 24 * 2;
    const uint32_t b_stride = 16 * 136 * 2;
    uint32_t a_off[4], b_off[4];
    {
        const int arow = lane & 15;
        const int acol = (lane >> 4) * 8;
        #pragma unroll
        for (int i = 0; i < 4; i++)
            a_off[i] = a_base + (uint32_t)(((warp_m * 64 + i * 16 + arow) * 24 + acol) * 2);
        const int brow = lane & 15;
        #pragma unroll
        for (int j = 0; j < 4; j++)
            b_off[j] = b_base + (uint32_t)((brow * 136 + warp_n * 32 + j * 8) * 2);
    }

    load_regs(0);
    sts(0);
    __syncthreads();

    for (int t = 0; t < KT; t++) {
        const int buf = t & 1;
        if (t + 1 < KT) load_regs(t + 1);

        uint32_t af[4][4], bf[4][2];
        #pragma unroll
        for (int i = 0; i < 4; i++) ldmatrix_x4(af[i], a_off[i] + buf * a_stride);
        #pragma unroll
        for (int j = 0; j < 4; j++) ldmatrix_x2t(bf[j], b_off[j] + buf * b_stride);
        #pragma unroll
        for (int i = 0; i < 4; i++)
            #pragma unroll
            for (int j = 0; j < 4; j++)
                mma_f16(acc[i][j], af[i], bf[j]);

        if (t + 1 < KT) {
            sts(buf ^ 1);
            __syncthreads();
        }
    }

    const int lg = lane >> 2;
    const int lr = lane & 3;
    #pragma unroll
    for (int i = 0; i < 4; i++) {
        const int r0 = rowBase + warp_m * 64 + i * 16 + lg;
        #pragma unroll
        for (int half = 0; half < 2; half++) {
            const int rr = r0 + half * 8;
            if (rr >= M) continue;
            #pragma unroll
            for (int j = 0; j < 4; j++) {
                const int cc = colBase + warp_n * 32 + j * 8 + lr * 2;
                float v0 = acc[i][j][half * 2 + 0];
                float v1 = acc[i][j][half * 2 + 1];
                if (USE_BIAS) { v0 += bias[cc]; v1 += bias[cc + 1]; }
                if (OUT_HALF) {
                    __half2* C = (__half2*)Cv;
                    C[((size_t)rr * N + cc) >> 1] = __floats2half2_rn(v0, v1);
                } else {
                    float* C = (float*)Cv;
                    *(float2*)(C + (size_t)rr * N + cc) = make_float2(v0, v1);
                }
            }
        }
    }
}

// ---------------- CSR gather aggregation (fp16 in, fp32 accumulate) ----------------
// warp per destination; lane owns 8 consecutive features (one uint4 = 8 halves).
// Edge records staged through smem; per-edge LDS.64 broadcast (no shfl).
// L1: out = relu(agg + b1) -> fp16.   L2: out = agg -> fp32.
template <bool L1>
__global__ __launch_bounds__(256) void gather_kernel(
    const __half* __restrict__ srcfeat,
    const float* __restrict__ bias,
    __half* __restrict__ out_h,
    float* __restrict__ out_f)
{
    __shared__ float2 se[8][32];
    const int w    = threadIdx.x >> 5;
    const int warp = blockIdx.x * 8 + w;
    const int lane = threadIdx.x & 31;
    if (warp >= N_NODES) return;

    const int start = g_rowptr[warp];
    const int end   = start + g_cnt[warp];
    const float di  = g_dis[warp];
    const float nn  = di * di;

    float acc[8];

    // self term
    {
        uint4 raw = __ldg((const uint4*)(srcfeat + (size_t)warp * MID_DIM) + lane);
        const __half2* hp = (const __half2*)&raw;
        #pragma unroll
        for (int q = 0; q < 4; q++) {
            float2 f = __half22float2(hp[q]);
            acc[2 * q]     = f.x * nn;
            acc[2 * q + 1] = f.y * nn;
        }
    }

    // edges: stage 32 records in smem, LDS broadcast per edge
    for (int base = start; base < end; base += 32) {
        const int rem = min(32, end - base);
        if (base + lane < end) se[w][lane] = __ldg(&g_epack[base + lane]);
        __syncwarp();
        #pragma unroll 4
        for (int j = 0; j < rem; j++) {
            const float2 e = se[w][j];
            const int   s  = __float_as_int(e.x);
            const float wt = e.y;
            uint4 raw = __ldg((const uint4*)(srcfeat + (size_t)s * MID_DIM) + lane);
            const __half2* hp = (const __half2*)&raw;
            #pragma unroll
            for (int q = 0; q < 4; q++) {
                float2 f = __half22float2(hp[q]);
                acc[2 * q]     = fmaf(wt, f.x, acc[2 * q]);
                acc[2 * q + 1] = fmaf(wt, f.y, acc[2 * q + 1]);
            }
        }
        __syncwarp();
    }

    const int c8 = lane * 8;
    if (L1) {
        float4 bb0 = *(const float4*)(bias + c8);
        float4 bb1 = *(const float4*)(bias + c8 + 4);
        float b[8] = {bb0.x, bb0.y, bb0.z, bb0.w, bb1.x, bb1.y, bb1.z, bb1.w};
        uint4 outv;
        __half2* op = (__half2*)&outv;
        #pragma unroll
        for (int q = 0; q < 4; q++) {
            float v0 = fmaxf(acc[2 * q]     + b[2 * q],     0.f);
            float v1 = fmaxf(acc[2 * q + 1] + b[2 * q + 1], 0.f);
            op[q] = __floats2half2_rn(v0, v1);
        }
        ((uint4*)(out_h + (size_t)warp * MID_DIM))[lane] = outv;
    } else {
        float4* drow = (float4*)(out_f + (size_t)warp * MID_DIM);
        drow[2 * lane]     = make_float4(acc[0], acc[1], acc[2], acc[3]);
        drow[2 * lane + 1] = make_float4(acc[4], acc[5], acc[6], acc[7]);
    }
}

// ---------------- launch ----------------
extern "C" void kernel_launch(void* const* d_in, const int* in_sizes, int n_in,
                              void* d_out, int out_size)
{
    const float* x  = (const float*)d_in[0];
    const void*  ei = d_in[1];
    const float* W1 = (const float*)d_in[2];
    const float* b1 = (const float*)d_in[3];
    const float* W2 = (const float*)d_in[4];
    const float* b2 = (const float*)d_in[5];
    float* out = (float*)d_out;

    __half *xw, *h;
    float *agg2;
    cudaGetSymbolAddress((void**)&xw,   g_xw);
    cudaGetSymbolAddress((void**)&h,    g_h);
    cudaGetSymbolAddress((void**)&agg2, g_agg2);

    const int nb_nodes = (N_NODES + 255) / 256;
    const int nb_edges = (N_EDGES + 255) / 256;
    const int mblocks = (N_NODES + 127) / 128;
    const int gblocks = (N_NODES + 7) / 8;

    // launches 1-3
    detect_kernel<<<1, 32>>>((const int*)ei);
    zero_cnt_kernel<<<nb_nodes, 256>>>();
    hist_kernel<<<nb_edges, 256>>>(ei);

    // launch 4 (ncu capture slot): GEMM1 xw = x@W1 (fp16 out)
    gemm_f16_kernel<false, true><<<dim3(MID_DIM / 128, mblocks), 256>>>(
        x, W1, nullptr, xw, N_NODES, MID_DIM, IN_DIM);

    // CSR build (5-9)
    dis_kernel<<<nb_nodes, 256>>>();
    scan1_kernel<<<NBLK_SCAN, 256>>>();
    scan2_kernel<<<1, 256>>>();
    scan3_kernel<<<NBLK_SCAN, 256>>>();
    scatter_kernel<<<nb_edges, 256>>>(ei);

    // layer 1 aggregation: h = relu(A_norm xw + b1) (fp16 out)
    gather_kernel<true><<<gblocks, 256>>>(xw, b1, h, nullptr);

    // layer 2: agg2 = A_norm h (fp32); out = agg2@W2 + b2
    gather_kernel<false><<<gblocks, 256>>>(h, nullptr, nullptr, agg2);
    gemm_f16_kernel<true, false><<<dim3(IN_DIM / 128, mblocks), 256>>>(
        agg2, W2, b2, out, N_NODES, IN_DIM, MID_DIM);
}

// round 9
// speedup vs baseline: 4.6923x; 1.1299x over previous
#include <cuda_runtime.h>
#include <cuda_fp16.h>
#include <cstdint>

#define N_NODES 50000
#define N_EDGES 1600000
#define IN_DIM  1024
#define MID_DIM 256
#define NBLK_SCAN ((N_NODES + 255) / 256)   // 196

// ---------------- scratch (device globals; no allocs allowed) ----------------
__device__ __align__(16) float  g_dis[N_NODES];
__device__ __align__(16) __half g_xh  [(size_t)N_NODES * IN_DIM];   // fp16(x)
__device__ __align__(16) __half g_w1h [(size_t)IN_DIM * MID_DIM];   // fp16(W1)
__device__ __align__(16) __half g_w2h [(size_t)MID_DIM * IN_DIM];   // fp16(W2)
__device__ __align__(16) __half g_xw  [(size_t)N_NODES * MID_DIM];  // x@W1
__device__ __align__(16) __half g_h   [(size_t)N_NODES * MID_DIM];  // relu(A xw + b1)
__device__ __align__(16) __half g_ag2 [(size_t)N_NODES * MID_DIM];  // A h
__device__ int    g_cnt[N_NODES];
__device__ int    g_rowptr[N_NODES];
__device__ int    g_cur[N_NODES];
__device__ int    g_bsum[NBLK_SCAN];
__device__ __align__(8) float2 g_epack[N_EDGES];  // {src_as_float_bits, norm}
__device__ int    g_is64;

// ---------------- helpers ----------------
__device__ __forceinline__ uint32_t smem_u32(const void* p) {
    uint32_t a;
    asm("{ .reg .u64 t; cvta.to.shared.u64 t, %1; cvt.u32.u64 %0, t; }"
        : "=r"(a) : "l"(p));
    return a;
}
__device__ __forceinline__ void ldmatrix_x4(uint32_t* r, uint32_t addr) {
    asm volatile("ldmatrix.sync.aligned.m8n8.x4.shared.b16 {%0,%1,%2,%3}, [%4];"
                 : "=r"(r[0]), "=r"(r[1]), "=r"(r[2]), "=r"(r[3]) : "r"(addr));
}
__device__ __forceinline__ void ldmatrix_x2t(uint32_t* r, uint32_t addr) {
    asm volatile("ldmatrix.sync.aligned.m8n8.x2.trans.shared.b16 {%0,%1}, [%2];"
                 : "=r"(r[0]), "=r"(r[1]) : "r"(addr));
}
__device__ __forceinline__ void mma_f16(float* c, const uint32_t* a, const uint32_t* b) {
    asm volatile(
        "mma.sync.aligned.m16n8k16.row.col.f32.f16.f16.f32 "
        "{%0,%1,%2,%3}, {%4,%5,%6,%7}, {%8,%9}, {%0,%1,%2,%3};"
        : "+f"(c[0]), "+f"(c[1]), "+f"(c[2]), "+f"(c[3])
        : "r"(a[0]), "r"(a[1]), "r"(a[2]), "r"(a[3]), "r"(b[0]), "r"(b[1]));
}
__device__ __forceinline__ void cp_async16(uint32_t dst, const void* src, int nbytes) {
    asm volatile("cp.async.ca.shared.global [%0], [%1], 16, %2;"
                 :: "r"(dst), "l"(src), "r"(nbytes));
}
__device__ __forceinline__ void cp_commit() {
    asm volatile("cp.async.commit_group;");
}
__device__ __forceinline__ void cp_wait2() {
    asm volatile("cp.async.wait_group 2;");
}

// ---------------- fp32 -> fp16 conversion (8 elts/thread) ----------------
__global__ void conv_half_kernel(const float4* __restrict__ src,
                                 uint4* __restrict__ dst, int n8) {
    int i = blockIdx.x * blockDim.x + threadIdx.x;
    if (i >= n8) return;
    float4 a = __ldg(src + 2 * i);
    float4 b = __ldg(src + 2 * i + 1);
    uint4 o;
    ((__half2*)&o)[0] = __floats2half2_rn(a.x, a.y);
    ((__half2*)&o)[1] = __floats2half2_rn(a.z, a.w);
    ((__half2*)&o)[2] = __floats2half2_rn(b.x, b.y);
    ((__half2*)&o)[3] = __floats2half2_rn(b.z, b.w);
    dst[i] = o;
}

// ---------------- edge-index dtype detection ----------------
__global__ void detect_kernel(const int* __restrict__ ei_words) {
    if (threadIdx.x == 0 && blockIdx.x == 0) {
        int is64 = 1;
        #pragma unroll 1
        for (int i = 1; i < 512; i += 2)
            if (ei_words[i] != 0) { is64 = 0; break; }
        g_is64 = is64;
    }
}
__device__ __forceinline__ int edge_node(const void* ei, long long idx, int is64) {
    if (is64) return (int)((const long long*)ei)[idx];
    return ((const int*)ei)[idx];
}

// ---------------- CSR build ----------------
__global__ void zero_cnt_kernel() {
    int i = blockIdx.x * blockDim.x + threadIdx.x;
    if (i < N_NODES) g_cnt[i] = 0;
}
__global__ void hist_kernel(const void* __restrict__ ei) {
    int e = blockIdx.x * blockDim.x + threadIdx.x;
    if (e >= N_EDGES) return;
    int d = edge_node(ei, (long long)e + N_EDGES, g_is64);
    atomicAdd(&g_cnt[d], 1);
}
__global__ void dis_kernel() {
    int i = blockIdx.x * blockDim.x + threadIdx.x;
    if (i < N_NODES) g_dis[i] = rsqrtf((float)(g_cnt[i] + 1));
}
__global__ void scan1_kernel() {
    __shared__ int sh[256];
    int i = blockIdx.x * 256 + threadIdx.x;
    int v = (i < N_NODES) ? g_cnt[i] : 0;
    sh[threadIdx.x] = v;
    __syncthreads();
    #pragma unroll
    for (int off = 1; off < 256; off <<= 1) {
        int t = (threadIdx.x >= off) ? sh[threadIdx.x - off] : 0;
        __syncthreads();
        sh[threadIdx.x] += t;
        __syncthreads();
    }
    if (i < N_NODES) g_rowptr[i] = sh[threadIdx.x];
    if (threadIdx.x == 255) g_bsum[blockIdx.x] = sh[255];
}
__global__ void scan2_kernel() {
    __shared__ int sh[256];
    int v = (threadIdx.x < NBLK_SCAN) ? g_bsum[threadIdx.x] : 0;
    sh[threadIdx.x] = v;
    __syncthreads();
    #pragma unroll
    for (int off = 1; off < 256; off <<= 1) {
        int t = (threadIdx.x >= off) ? sh[threadIdx.x - off] : 0;
        __syncthreads();
        sh[threadIdx.x] += t;
        __syncthreads();
    }
    if (threadIdx.x < NBLK_SCAN) g_bsum[threadIdx.x] = sh[threadIdx.x] - v;
}
__global__ void scan3_kernel() {
    int i = blockIdx.x * 256 + threadIdx.x;
    if (i < N_NODES) {
        int ex = g_rowptr[i] - g_cnt[i] + g_bsum[blockIdx.x];
        g_rowptr[i] = ex;
        g_cur[i] = ex;
    }
}
__global__ void scatter_kernel(const void* __restrict__ ei) {
    int e = blockIdx.x * blockDim.x + threadIdx.x;
    if (e >= N_EDGES) return;
    int is64 = g_is64;
    int s = edge_node(ei, e, is64);
    int d = edge_node(ei, (long long)e + N_EDGES, is64);
    int pos = atomicAdd(&g_cur[d], 1);
    g_epack[pos] = make_float2(__int_as_float(s), g_dis[s] * g_dis[d]);
}

// ---------------- fp16 mma.sync GEMM with cp.async 4-stage pipeline ----------------
// C[M,N] = A[M,K] @ B[K,N] (+bias). A,B fp16 in GMEM. BM=128, BN=128, BK=16.
// 8 warps: warp_m = wid&1 (64 rows), warp_n = wid>>1 (32 cols); 4x4 m16n8k16/warp.
// Stages: As stride 24h (48B, 16B-aligned, conflict-free), Bs stride 136h (272B).
template <bool USE_BIAS, bool OUT_HALF>
__global__ __launch_bounds__(256) void gemm_f16_kernel(
    const __half* __restrict__ A, const __half* __restrict__ B,
    const float* __restrict__ bias, void* __restrict__ Cv,
    int M, int N, int K)
{
    __shared__ __align__(16) __half As[4][128][24];
    __shared__ __align__(16) __half Bs[4][16][136];

    const int tid  = threadIdx.x;
    const int wid  = tid >> 5;
    const int lane = tid & 31;
    const int warp_m = wid & 1;
    const int warp_n = wid >> 1;
    const int rowBase = blockIdx.y * 128;
    const int colBase = blockIdx.x * 128;
    const int KT = K / 16;

    // staging: 1 x 16B chunk of A + 1 of B per thread per stage
    const int ar  = tid >> 1;           // 0..127
    const int ac  = (tid & 1) * 8;      // 0 or 8
    const int brr = tid >> 4;           // 0..15
    const int bcc = (tid & 15) * 8;     // 0..120

    const uint32_t as_base = smem_u32(&As[0][0][0]);
    const uint32_t bs_base = smem_u32(&Bs[0][0][0]);
    const uint32_t a_stage = 128 * 24 * 2;
    const uint32_t b_stage = 16 * 136 * 2;

    const uint32_t a_dst = as_base + (uint32_t)((ar * 24 + ac) * 2);
    const uint32_t b_dst = bs_base + (uint32_t)((brr * 136 + bcc) * 2);
    const int a_row_ok = (rowBase + ar < M) ? 16 : 0;
    const __half* a_src = A + (size_t)(a_row_ok ? (rowBase + ar) : 0) * K + ac;
    const __half* b_src = B + (size_t)brr * N + colBase + bcc;

    auto issue_stage = [&](int s, int t) {
        cp_async16(a_dst + s * a_stage, a_src + t * 16, a_row_ok);
        cp_async16(b_dst + s * b_stage, b_src + (size_t)t * 16 * N, 16);
    };

    float acc[4][4][4];
    #pragma unroll
    for (int i = 0; i < 4; i++)
        #pragma unroll
        for (int j = 0; j < 4; j++)
            #pragma unroll
            for (int r = 0; r < 4; r++) acc[i][j][r] = 0.f;

    // fragment ldmatrix addresses
    uint32_t a_off[4], b_off[4];
    {
        const int arow = lane & 15;
        const int acol = (lane >> 4) * 8;
        #pragma unroll
        for (int i = 0; i < 4; i++)
            a_off[i] = as_base + (uint32_t)(((warp_m * 64 + i * 16 + arow) * 24 + acol) * 2);
        #pragma unroll
        for (int j = 0; j < 4; j++)
            b_off[j] = bs_base + (uint32_t)(((lane & 15) * 136 + warp_n * 32 + j * 8) * 2);
    }

    // prologue: stages 0..2 in flight
    #pragma unroll
    for (int s = 0; s < 3; s++) { issue_stage(s, s); cp_commit(); }

    for (int t = 0; t < KT; t++) {
        cp_wait2();
        __syncthreads();
        if (t + 3 < KT) issue_stage((t + 3) & 3, t + 3);
        cp_commit();

        const int buf = t & 3;
        uint32_t af[4][4], bf[4][2];
        #pragma unroll
        for (int i = 0; i < 4; i++) ldmatrix_x4(af[i], a_off[i] + buf * a_stage);
        #pragma unroll
        for (int j = 0; j < 4; j++) ldmatrix_x2t(bf[j], b_off[j] + buf * b_stage);
        #pragma unroll
        for (int i = 0; i < 4; i++)
            #pragma unroll
            for (int j = 0; j < 4; j++)
                mma_f16(acc[i][j], af[i], bf[j]);
    }

    const int lg = lane >> 2;
    const int lr = lane & 3;
    #pragma unroll
    for (int i = 0; i < 4; i++) {
        const int r0 = rowBase + warp_m * 64 + i * 16 + lg;
        #pragma unroll
        for (int half = 0; half < 2; half++) {
            const int rr = r0 + half * 8;
            if (rr >= M) continue;
            #pragma unroll
            for (int j = 0; j < 4; j++) {
                const int cc = colBase + warp_n * 32 + j * 8 + lr * 2;
                float v0 = acc[i][j][half * 2 + 0];
                float v1 = acc[i][j][half * 2 + 1];
                if (USE_BIAS) { v0 += bias[cc]; v1 += bias[cc + 1]; }
                if (OUT_HALF) {
                    __half2* C = (__half2*)Cv;
                    C[((size_t)rr * N + cc) >> 1] = __floats2half2_rn(v0, v1);
                } else {
                    float* C = (float*)Cv;
                    *(float2*)(C + (size_t)rr * N + cc) = make_float2(v0, v1);
                }
            }
        }
    }
}

// ---------------- CSR gather aggregation (fp16 in, fp32 accumulate, fp16 out) ----------------
// warp per destination; lane owns 8 consecutive features (one uint4 = 8 halves).
// L1: out = relu(agg + b1). L2: out = agg.
template <bool L1>
__global__ __launch_bounds__(256) void gather_kernel(
    const __half* __restrict__ srcfeat,
    const float* __restrict__ bias,
    __half* __restrict__ out)
{
    __shared__ float2 se[8][32];
    const int w    = threadIdx.x >> 5;
    const int warp = blockIdx.x * 8 + w;
    const int lane = threadIdx.x & 31;
    if (warp >= N_NODES) return;

    const int start = g_rowptr[warp];
    const int end   = start + g_cnt[warp];
    const float di  = g_dis[warp];
    const float nn  = di * di;

    float acc[8];

    // self term
    {
        uint4 raw = __ldg((const uint4*)(srcfeat + (size_t)warp * MID_DIM) + lane);
        const __half2* hp = (const __half2*)&raw;
        #pragma unroll
        for (int q = 0; q < 4; q++) {
            float2 f = __half22float2(hp[q]);
            acc[2 * q]     = f.x * nn;
            acc[2 * q + 1] = f.y * nn;
        }
    }

    // edges: stage 32 records in smem, LDS broadcast per edge
    for (int base = start; base < end; base += 32) {
        const int rem = min(32, end - base);
        if (base + lane < end) se[w][lane] = __ldg(&g_epack[base + lane]);
        __syncwarp();
        #pragma unroll 4
        for (int j = 0; j < rem; j++) {
            const float2 e = se[w][j];
            const int   s  = __float_as_int(e.x);
            const float wt = e.y;
            uint4 raw = __ldg((const uint4*)(srcfeat + (size_t)s * MID_DIM) + lane);
            const __half2* hp = (const __half2*)&raw;
            #pragma unroll
            for (int q = 0; q < 4; q++) {
                float2 f = __half22float2(hp[q]);
                acc[2 * q]     = fmaf(wt, f.x, acc[2 * q]);
                acc[2 * q + 1] = fmaf(wt, f.y, acc[2 * q + 1]);
            }
        }
        __syncwarp();
    }

    uint4 outv;
    __half2* op = (__half2*)&outv;
    if (L1) {
        const int c8 = lane * 8;
        float4 bb0 = *(const float4*)(bias + c8);
        float4 bb1 = *(const float4*)(bias + c8 + 4);
        float b[8] = {bb0.x, bb0.y, bb0.z, bb0.w, bb1.x, bb1.y, bb1.z, bb1.w};
        #pragma unroll
        for (int q = 0; q < 4; q++) {
            float v0 = fmaxf(acc[2 * q]     + b[2 * q],     0.f);
            float v1 = fmaxf(acc[2 * q + 1] + b[2 * q + 1], 0.f);
            op[q] = __floats2half2_rn(v0, v1);
        }
    } else {
        #pragma unroll
        for (int q = 0; q < 4; q++)
            op[q] = __floats2half2_rn(acc[2 * q], acc[2 * q + 1]);
    }
    ((uint4*)(out + (size_t)warp * MID_DIM))[lane] = outv;
}

// ---------------- launch ----------------
extern "C" void kernel_launch(void* const* d_in, const int* in_sizes, int n_in,
                              void* d_out, int out_size)
{
    const float* x  = (const float*)d_in[0];
    const void*  ei = d_in[1];
    const float* W1 = (const float*)d_in[2];
    const float* b1 = (const float*)d_in[3];
    const float* W2 = (const float*)d_in[4];
    const float* b2 = (const float*)d_in[5];
    float* out = (float*)d_out;

    __half *xh, *w1h, *w2h, *xw, *h, *ag2;
    cudaGetSymbolAddress((void**)&xh,  g_xh);
    cudaGetSymbolAddress((void**)&w1h, g_w1h);
    cudaGetSymbolAddress((void**)&w2h, g_w2h);
    cudaGetSymbolAddress((void**)&xw,  g_xw);
    cudaGetSymbolAddress((void**)&h,   g_h);
    cudaGetSymbolAddress((void**)&ag2, g_ag2);

    const int nb_nodes = (N_NODES + 255) / 256;
    const int nb_edges = (N_EDGES + 255) / 256;
    const int mblocks = (N_NODES + 127) / 128;
    const int gblocks = (N_NODES + 7) / 8;

    // 1-3: fp16 conversions
    {
        int n8x = (N_NODES * IN_DIM) / 8;
        conv_half_kernel<<<(n8x + 255) / 256, 256>>>((const float4*)x, (uint4*)xh, n8x);
        int n8w = (IN_DIM * MID_DIM) / 8;
        conv_half_kernel<<<(n8w + 255) / 256, 256>>>((const float4*)W1, (uint4*)w1h, n8w);
        conv_half_kernel<<<(n8w + 255) / 256, 256>>>((const float4*)W2, (uint4*)w2h, n8w);
    }

    // 4 (ncu capture slot): GEMM1 xw = x@W1 (fp16 out)
    gemm_f16_kernel<false, true><<<dim3(MID_DIM / 128, mblocks), 256>>>(
        xh, w1h, nullptr, xw, N_NODES, MID_DIM, IN_DIM);

    // CSR build
    detect_kernel<<<1, 32>>>((const int*)ei);
    zero_cnt_kernel<<<nb_nodes, 256>>>();
    hist_kernel<<<nb_edges, 256>>>(ei);
    dis_kernel<<<nb_nodes, 256>>>();
    scan1_kernel<<<NBLK_SCAN, 256>>>();
    scan2_kernel<<<1, 256>>>();
    scan3_kernel<<<NBLK_SCAN, 256>>>();
    scatter_kernel<<<nb_edges, 256>>>(ei);

    // layer 1 aggregation: h = relu(A_norm xw + b1)
    gather_kernel<true><<<gblocks, 256>>>(xw, b1, h);

    // layer 2: ag2 = A_norm h ; out = ag2@W2 + b2
    gather_kernel<false><<<gblocks, 256>>>(h, nullptr, ag2);
    gemm_f16_kernel<true, false><<<dim3(IN_DIM / 128, mblocks), 256>>>(
        ag2, w2h, b2, out, N_NODES, IN_DIM, MID_DIM);
}

// round 10
// speedup vs baseline: 4.8068x; 1.0244x over previous
#include <cuda_runtime.h>
#include <cuda_fp16.h>
#include <cstdint>

#define N_NODES 50000
#define N_EDGES 1600000
#define IN_DIM  1024
#define MID_DIM 256
#define NBLK_SCAN ((N_NODES + 255) / 256)   // 196

// ---------------- scratch (device globals; no allocs allowed) ----------------
__device__ __align__(16) float  g_dis[N_NODES];
__device__ __align__(16) __half g_xh  [(size_t)N_NODES * IN_DIM];   // fp16(x)
__device__ __align__(16) __half g_w1h [(size_t)IN_DIM * MID_DIM];   // fp16(W1)
__device__ __align__(16) __half g_w2h [(size_t)MID_DIM * IN_DIM];   // fp16(W2)
__device__ __align__(16) __half g_xw  [(size_t)N_NODES * MID_DIM];  // x@W1
__device__ __align__(16) __half g_h   [(size_t)N_NODES * MID_DIM];  // relu(A xw + b1)
__device__ __align__(16) __half g_ag2 [(size_t)N_NODES * MID_DIM];  // A h
__device__ int    g_cnt[N_NODES];
__device__ int    g_rowptr[N_NODES];
__device__ int    g_cur[N_NODES];
__device__ int    g_bsum[NBLK_SCAN];
__device__ __align__(8) float2 g_epack[N_EDGES];  // {src_as_float_bits, norm}
__device__ int    g_is64;

// ---------------- helpers ----------------
__device__ __forceinline__ uint32_t smem_u32(const void* p) {
    uint32_t a;
    asm("{ .reg .u64 t; cvta.to.shared.u64 t, %1; cvt.u32.u64 %0, t; }"
        : "=r"(a) : "l"(p));
    return a;
}
__device__ __forceinline__ void ldmatrix_x4(uint32_t* r, uint32_t addr) {
    asm volatile("ldmatrix.sync.aligned.m8n8.x4.shared.b16 {%0,%1,%2,%3}, [%4];"
                 : "=r"(r[0]), "=r"(r[1]), "=r"(r[2]), "=r"(r[3]) : "r"(addr));
}
__device__ __forceinline__ void ldmatrix_x2t(uint32_t* r, uint32_t addr) {
    asm volatile("ldmatrix.sync.aligned.m8n8.x2.trans.shared.b16 {%0,%1}, [%2];"
                 : "=r"(r[0]), "=r"(r[1]) : "r"(addr));
}
__device__ __forceinline__ void mma_f16(float* c, const uint32_t* a, const uint32_t* b) {
    asm volatile(
        "mma.sync.aligned.m16n8k16.row.col.f32.f16.f16.f32 "
        "{%0,%1,%2,%3}, {%4,%5,%6,%7}, {%8,%9}, {%0,%1,%2,%3};"
        : "+f"(c[0]), "+f"(c[1]), "+f"(c[2]), "+f"(c[3])
        : "r"(a[0]), "r"(a[1]), "r"(a[2]), "r"(a[3]), "r"(b[0]), "r"(b[1]));
}
__device__ __forceinline__ void cp_async16(uint32_t dst, const void* src, int nbytes) {
    asm volatile("cp.async.ca.shared.global [%0], [%1], 16, %2;"
                 :: "r"(dst), "l"(src), "r"(nbytes));
}
__device__ __forceinline__ void cp_commit() {
    asm volatile("cp.async.commit_group;");
}
__device__ __forceinline__ void cp_wait2() {
    asm volatile("cp.async.wait_group 2;");
}

// ---------------- fp32 -> fp16 conversion (8 elts/thread) ----------------
__global__ void conv_half_kernel(const float4* __restrict__ src,
                                 uint4* __restrict__ dst, int n8) {
    int i = blockIdx.x * blockDim.x + threadIdx.x;
    if (i >= n8) return;
    float4 a = __ldg(src + 2 * i);
    float4 b = __ldg(src + 2 * i + 1);
    uint4 o;
    ((__half2*)&o)[0] = __floats2half2_rn(a.x, a.y);
    ((__half2*)&o)[1] = __floats2half2_rn(a.z, a.w);
    ((__half2*)&o)[2] = __floats2half2_rn(b.x, b.y);
    ((__half2*)&o)[3] = __floats2half2_rn(b.z, b.w);
    dst[i] = o;
}

// ---------------- edge-index dtype detection ----------------
__global__ void detect_kernel(const int* __restrict__ ei_words) {
    if (threadIdx.x == 0 && blockIdx.x == 0) {
        int is64 = 1;
        #pragma unroll 1
        for (int i = 1; i < 512; i += 2)
            if (ei_words[i] != 0) { is64 = 0; break; }
        g_is64 = is64;
    }
}
__device__ __forceinline__ int edge_node(const void* ei, long long idx, int is64) {
    if (is64) return (int)((const long long*)ei)[idx];
    return ((const int*)ei)[idx];
}

// ---------------- CSR build ----------------
__global__ void zero_cnt_kernel() {
    int i = blockIdx.x * blockDim.x + threadIdx.x;
    if (i < N_NODES) g_cnt[i] = 0;
}
__global__ void hist_kernel(const void* __restrict__ ei) {
    int e = blockIdx.x * blockDim.x + threadIdx.x;
    if (e >= N_EDGES) return;
    int d = edge_node(ei, (long long)e + N_EDGES, g_is64);
    atomicAdd(&g_cnt[d], 1);
}
__global__ void dis_kernel() {
    int i = blockIdx.x * blockDim.x + threadIdx.x;
    if (i < N_NODES) g_dis[i] = rsqrtf((float)(g_cnt[i] + 1));
}
__global__ void scan1_kernel() {
    __shared__ int sh[256];
    int i = blockIdx.x * 256 + threadIdx.x;
    int v = (i < N_NODES) ? g_cnt[i] : 0;
    sh[threadIdx.x] = v;
    __syncthreads();
    #pragma unroll
    for (int off = 1; off < 256; off <<= 1) {
        int t = (threadIdx.x >= off) ? sh[threadIdx.x - off] : 0;
        __syncthreads();
        sh[threadIdx.x] += t;
        __syncthreads();
    }
    if (i < N_NODES) g_rowptr[i] = sh[threadIdx.x];
    if (threadIdx.x == 255) g_bsum[blockIdx.x] = sh[255];
}
__global__ void scan2_kernel() {
    __shared__ int sh[256];
    int v = (threadIdx.x < NBLK_SCAN) ? g_bsum[threadIdx.x] : 0;
    sh[threadIdx.x] = v;
    __syncthreads();
    #pragma unroll
    for (int off = 1; off < 256; off <<= 1) {
        int t = (threadIdx.x >= off) ? sh[threadIdx.x - off] : 0;
        __syncthreads();
        sh[threadIdx.x] += t;
        __syncthreads();
    }
    if (threadIdx.x < NBLK_SCAN) g_bsum[threadIdx.x] = sh[threadIdx.x] - v;
}
__global__ void scan3_kernel() {
    int i = blockIdx.x * 256 + threadIdx.x;
    if (i < N_NODES) {
        int ex = g_rowptr[i] - g_cnt[i] + g_bsum[blockIdx.x];
        g_rowptr[i] = ex;
        g_cur[i] = ex;
    }
}
__global__ void scatter_kernel(const void* __restrict__ ei) {
    int e = blockIdx.x * blockDim.x + threadIdx.x;
    if (e >= N_EDGES) return;
    int is64 = g_is64;
    int s = edge_node(ei, e, is64);
    int d = edge_node(ei, (long long)e + N_EDGES, is64);
    int pos = atomicAdd(&g_cur[d], 1);
    g_epack[pos] = make_float2(__int_as_float(s), g_dis[s] * g_dis[d]);
}

// ---------------- fp16 mma.sync GEMM, BM=128 BN=256 BK=16, cp.async 4-stage ----------------
// 8 warps as 2(m) x 4(n); 64x64 per warp = 4x8 m16n8k16, acc in 128 regs.
// As stride 24h (48B), Bs stride 264h (528B) — both 16B-aligned, conflict-free.
template <bool USE_BIAS, bool OUT_HALF>
__global__ __launch_bounds__(256) void gemm_f16_kernel(
    const __half* __restrict__ A, const __half* __restrict__ B,
    const float* __restrict__ bias, void* __restrict__ Cv,
    int M, int N, int K)
{
    __shared__ __align__(16) __half As[4][128][24];
    __shared__ __align__(16) __half Bs[4][16][264];

    const int tid  = threadIdx.x;
    const int wid  = tid >> 5;
    const int lane = tid & 31;
    const int warp_m = wid & 1;
    const int warp_n = wid >> 1;         // 0..3
    const int rowBase = blockIdx.y * 128;
    const int colBase = blockIdx.x * 256;
    const int KT = K / 16;

    // staging: A 1 chunk/thread, B 2 chunks/thread (16B each)
    const int ar  = tid >> 1;            // 0..127
    const int ac  = (tid & 1) * 8;       // 0 or 8
    const uint32_t as_base = smem_u32(&As[0][0][0]);
    const uint32_t bs_base = smem_u32(&Bs[0][0][0]);
    const uint32_t a_stage = 128 * 24 * 2;
    const uint32_t b_stage = 16 * 264 * 2;

    const uint32_t a_dst = as_base + (uint32_t)((ar * 24 + ac) * 2);
    const int a_row_ok = (rowBase + ar < M) ? 16 : 0;
    const __half* a_src = A + (size_t)(a_row_ok ? (rowBase + ar) : 0) * K + ac;

    // B chunk c (c = tid, tid+256): row = c>>5 (0..15), col = (c&31)*8
    const int br0 = tid >> 5,         bc0 = (tid & 31) * 8;
    const int br1 = (tid + 256) >> 5, bc1 = ((tid + 256) & 31) * 8;
    const uint32_t b_dst0 = bs_base + (uint32_t)((br0 * 264 + bc0) * 2);
    const uint32_t b_dst1 = bs_base + (uint32_t)((br1 * 264 + bc1) * 2);
    const __half* b_src0 = B + (size_t)br0 * N + colBase + bc0;
    const __half* b_src1 = B + (size_t)br1 * N + colBase + bc1;

    auto issue_stage = [&](int s, int t) {
        cp_async16(a_dst + s * a_stage, a_src + t * 16, a_row_ok);
        cp_async16(b_dst0 + s * b_stage, b_src0 + (size_t)t * 16 * N, 16);
        cp_async16(b_dst1 + s * b_stage, b_src1 + (size_t)t * 16 * N, 16);
    };

    float acc[4][8][4];
    #pragma unroll
    for (int i = 0; i < 4; i++)
        #pragma unroll
        for (int j = 0; j < 8; j++)
            #pragma unroll
            for (int r = 0; r < 4; r++) acc[i][j][r] = 0.f;

    // fragment ldmatrix addresses
    uint32_t a_off[4], b_off[8];
    {
        const int arow = lane & 15;
        const int acol = (lane >> 4) * 8;
        #pragma unroll
        for (int i = 0; i < 4; i++)
            a_off[i] = as_base + (uint32_t)(((warp_m * 64 + i * 16 + arow) * 24 + acol) * 2);
        #pragma unroll
        for (int j = 0; j < 8; j++)
            b_off[j] = bs_base + (uint32_t)(((lane & 15) * 264 + warp_n * 64 + j * 8) * 2);
    }

    // prologue: stages 0..2 in flight
    #pragma unroll
    for (int s = 0; s < 3; s++) { issue_stage(s, s); cp_commit(); }

    for (int t = 0; t < KT; t++) {
        cp_wait2();
        __syncthreads();
        if (t + 3 < KT) issue_stage((t + 3) & 3, t + 3);
        cp_commit();

        const int buf = t & 3;
        uint32_t af[4][4];
        #pragma unroll
        for (int i = 0; i < 4; i++) ldmatrix_x4(af[i], a_off[i] + buf * a_stage);

        #pragma unroll
        for (int jb = 0; jb < 2; jb++) {
            uint32_t bf[4][2];
            #pragma unroll
            for (int jj = 0; jj < 4; jj++)
                ldmatrix_x2t(bf[jj], b_off[jb * 4 + jj] + buf * b_stage);
            #pragma unroll
            for (int i = 0; i < 4; i++)
                #pragma unroll
                for (int jj = 0; jj < 4; jj++)
                    mma_f16(acc[i][jb * 4 + jj], af[i], bf[jj]);
        }
    }

    const int lg = lane >> 2;
    const int lr = lane & 3;
    #pragma unroll
    for (int i = 0; i < 4; i++) {
        const int r0 = rowBase + warp_m * 64 + i * 16 + lg;
        #pragma unroll
        for (int half = 0; half < 2; half++) {
            const int rr = r0 + half * 8;
            if (rr >= M) continue;
            #pragma unroll
            for (int j = 0; j < 8; j++) {
                const int cc = colBase + warp_n * 64 + j * 8 + lr * 2;
                float v0 = acc[i][j][half * 2 + 0];
                float v1 = acc[i][j][half * 2 + 1];
                if (USE_BIAS) { v0 += bias[cc]; v1 += bias[cc + 1]; }
                if (OUT_HALF) {
                    __half2* C = (__half2*)Cv;
                    C[((size_t)rr * N + cc) >> 1] = __floats2half2_rn(v0, v1);
                } else {
                    float* C = (float*)Cv;
                    *(float2*)(C + (size_t)rr * N + cc) = make_float2(v0, v1);
                }
            }
        }
    }
}

// ---------------- CSR gather aggregation (fp16 in, fp32 accumulate, fp16 out) ----------------
template <bool L1>
__global__ __launch_bounds__(256) void gather_kernel(
    const __half* __restrict__ srcfeat,
    const float* __restrict__ bias,
    __half* __restrict__ out)
{
    __shared__ float2 se[8][32];
    const int w    = threadIdx.x >> 5;
    const int warp = blockIdx.x * 8 + w;
    const int lane = threadIdx.x & 31;
    if (warp >= N_NODES) return;

    const int start = g_rowptr[warp];
    const int end   = start + g_cnt[warp];
    const float di  = g_dis[warp];
    const float nn  = di * di;

    float acc[8];

    // self term
    {
        uint4 raw = __ldg((const uint4*)(srcfeat + (size_t)warp * MID_DIM) + lane);
        const __half2* hp = (const __half2*)&raw;
        #pragma unroll
        for (int q = 0; q < 4; q++) {
            float2 f = __half22float2(hp[q]);
            acc[2 * q]     = f.x * nn;
            acc[2 * q + 1] = f.y * nn;
        }
    }

    // edges: stage 32 records in smem, LDS broadcast per edge
    for (int base = start; base < end; base += 32) {
        const int rem = min(32, end - base);
        if (base + lane < end) se[w][lane] = __ldg(&g_epack[base + lane]);
        __syncwarp();
        #pragma unroll 4
        for (int j = 0; j < rem; j++) {
            const float2 e = se[w][j];
            const int   s  = __float_as_int(e.x);
            const float wt = e.y;
            uint4 raw = __ldg((const uint4*)(srcfeat + (size_t)s * MID_DIM) + lane);
            const __half2* hp = (const __half2*)&raw;
            #pragma unroll
            for (int q = 0; q < 4; q++) {
                float2 f = __half22float2(hp[q]);
                acc[2 * q]     = fmaf(wt, f.x, acc[2 * q]);
                acc[2 * q + 1] = fmaf(wt, f.y, acc[2 * q + 1]);
            }
        }
        __syncwarp();
    }

    uint4 outv;
    __half2* op = (__half2*)&outv;
    if (L1) {
        const int c8 = lane * 8;
        float4 bb0 = *(const float4*)(bias + c8);
        float4 bb1 = *(const float4*)(bias + c8 + 4);
        float b[8] = {bb0.x, bb0.y, bb0.z, bb0.w, bb1.x, bb1.y, bb1.z, bb1.w};
        #pragma unroll
        for (int q = 0; q < 4; q++) {
            float v0 = fmaxf(acc[2 * q]     + b[2 * q],     0.f);
            float v1 = fmaxf(acc[2 * q + 1] + b[2 * q + 1], 0.f);
            op[q] = __floats2half2_rn(v0, v1);
        }
    } else {
        #pragma unroll
        for (int q = 0; q < 4; q++)
            op[q] = __floats2half2_rn(acc[2 * q], acc[2 * q + 1]);
    }
    ((uint4*)(out + (size_t)warp * MID_DIM))[lane] = outv;
}

// ---------------- launch ----------------
extern "C" void kernel_launch(void* const* d_in, const int* in_sizes, int n_in,
                              void* d_out, int out_size)
{
    const float* x  = (const float*)d_in[0];
    const void*  ei = d_in[1];
    const float* W1 = (const float*)d_in[2];
    const float* b1 = (const float*)d_in[3];
    const float* W2 = (const float*)d_in[4];
    const float* b2 = (const float*)d_in[5];
    float* out = (float*)d_out;

    __half *xh, *w1h, *w2h, *xw, *h, *ag2;
    cudaGetSymbolAddress((void**)&xh,  g_xh);
    cudaGetSymbolAddress((void**)&w1h, g_w1h);
    cudaGetSymbolAddress((void**)&w2h, g_w2h);
    cudaGetSymbolAddress((void**)&xw,  g_xw);
    cudaGetSymbolAddress((void**)&h,   g_h);
    cudaGetSymbolAddress((void**)&ag2, g_ag2);

    const int nb_nodes = (N_NODES + 255) / 256;
    const int nb_edges = (N_EDGES + 255) / 256;
    const int mblocks = (N_NODES + 127) / 128;
    const int gblocks = (N_NODES + 7) / 8;

    // 1-3: fp16 conversions
    {
        int n8x = (N_NODES * IN_DIM) / 8;
        conv_half_kernel<<<(n8x + 255) / 256, 256>>>((const float4*)x, (uint4*)xh, n8x);
        int n8w = (IN_DIM * MID_DIM) / 8;
        conv_half_kernel<<<(n8w + 255) / 256, 256>>>((const float4*)W1, (uint4*)w1h, n8w);
        conv_half_kernel<<<(n8w + 255) / 256, 256>>>((const float4*)W2, (uint4*)w2h, n8w);
    }

    // 4 (ncu capture slot): GEMM1 xw = x@W1 (fp16 out)
    gemm_f16_kernel<false, true><<<dim3(MID_DIM / 256, mblocks), 256>>>(
        xh, w1h, nullptr, xw, N_NODES, MID_DIM, IN_DIM);

    // CSR build
    detect_kernel<<<1, 32>>>((const int*)ei);
    zero_cnt_kernel<<<nb_nodes, 256>>>();
    hist_kernel<<<nb_edges, 256>>>(ei);
    dis_kernel<<<nb_nodes, 256>>>();
    scan1_kernel<<<NBLK_SCAN, 256>>>();
    scan2_kernel<<<1, 256>>>();
    scan3_kernel<<<NBLK_SCAN, 256>>>();
    scatter_kernel<<<nb_edges, 256>>>(ei);

    // layer 1 aggregation: h = relu(A_norm xw + b1)
    gather_kernel<true><<<gblocks, 256>>>(xw, b1, h);

    // layer 2: ag2 = A_norm h ; out = ag2@W2 + b2
    gather_kernel<false><<<gblocks, 256>>>(h, nullptr, ag2);
    gemm_f16_kernel<true, false><<<dim3(IN_DIM / 256, mblocks), 256>>>(
        ag2, w2h, b2, out, N_NODES, IN_DIM, MID_DIM);
}